// round 8
// baseline (speedup 1.0000x reference)
#include <cuda_runtime.h>
#include <cuda_fp16.h>
#include <math.h>

// Problem constants
#define Bb      8
#define Nn      2048
#define Cc      256
#define Ee      32768
#define Hh      8
#define CO      64
#define BN_TOT  (Bb * Nn)          // 16384 nodes
#define F       (Hh * CO)          // 512 features
#define BE      (Bb * Ee)          // 262144 real edges
#define ET      (BE + BN_TOT)      // 278528 edges incl. self loops
#define NEG     0.2f

// ---------------- scratch (static device globals; no allocation) ----------------
__device__ __half g_xt[(size_t)BN_TOT * F];    // projected features, fp16, 16 MB
__device__ float  g_asrc[BN_TOT * Hh];         // per-node src attention dot (fp32)
__device__ float  g_adst[BN_TOT * Hh];         // per-node dst attention dot (fp32)
__device__ int    g_src[ET];
__device__ int    g_dst[ET];
__device__ int    g_cnt[BN_TOT];               // in-degree counts
__device__ int    g_rowptr[BN_TOT + 1];        // CSR row pointers (by dst)
__device__ int    g_ofs[BN_TOT];               // running offsets for place
__device__ int    g_csrc[ET];                  // CSR: src node per slot
__device__ int    g_is64;

// ---------------- detect edge dtype + zero counts (merged) ----------------------
__global__ void detect_zero_kernel(const unsigned* __restrict__ w) {
    int t = blockIdx.x * blockDim.x + threadIdx.x;
    if (t < BN_TOT) g_cnt[t] = 0;
    if (blockIdx.x == 0 && threadIdx.x < 32) {
        unsigned v = w[2 * threadIdx.x + 1];   // int64 => odd words zero
        unsigned all0 = __all_sync(0xffffffffu, v == 0u);
        if (threadIdx.x == 0) g_is64 = all0 ? 1 : 0;
    }
}

// ---------------- decode batched edges (+ self loops) and count in-degrees ------
__global__ void decode_count_kernel(const void* __restrict__ eiv) {
    int e = blockIdx.x * blockDim.x + threadIdx.x;
    if (e >= ET) return;
    int s, d;
    if (e < BE) {
        int k = e & (Ee - 1);
        int b = e >> 15;
        if (g_is64) {
            const long long* p = (const long long*)eiv;
            s = (int)p[k];
            d = (int)p[Ee + k];
        } else {
            const int* p = (const int*)eiv;
            s = p[k];
            d = p[Ee + k];
        }
        s += b * Nn;
        d += b * Nn;
    } else {
        s = d = e - BE;
    }
    g_src[e] = s;
    g_dst[e] = d;
    atomicAdd(&g_cnt[d], 1);
}

// ---------------- single-block exclusive scan over 16384 counts -----------------
__global__ void scan_kernel() {
    __shared__ int wsum[32];
    const int t = threadIdx.x;
    const int lane = t & 31;
    const int w = t >> 5;

    const int4* cin = (const int4*)g_cnt;
    int4 c0 = cin[t * 4 + 0];
    int4 c1 = cin[t * 4 + 1];
    int4 c2 = cin[t * 4 + 2];
    int4 c3 = cin[t * 4 + 3];
    int v[16] = {c0.x, c0.y, c0.z, c0.w, c1.x, c1.y, c1.z, c1.w,
                 c2.x, c2.y, c2.z, c2.w, c3.x, c3.y, c3.z, c3.w};

    int loc[16];
    int s = 0;
#pragma unroll
    for (int i = 0; i < 16; i++) { loc[i] = s; s += v[i]; }

    int inc = s;
#pragma unroll
    for (int o = 1; o < 32; o <<= 1) {
        int u = __shfl_up_sync(0xffffffffu, inc, o);
        if (lane >= o) inc += u;
    }
    if (lane == 31) wsum[w] = inc;
    __syncthreads();
    if (w == 0) {
        int x = wsum[lane];
#pragma unroll
        for (int o = 1; o < 32; o <<= 1) {
            int u = __shfl_up_sync(0xffffffffu, x, o);
            if (lane >= o) x += u;
        }
        wsum[lane] = x;
    }
    __syncthreads();

    int base_excl = (inc - s) + (w > 0 ? wsum[w - 1] : 0);

    int4* rp = (int4*)g_rowptr;
    int4* op = (int4*)g_ofs;
#pragma unroll
    for (int i = 0; i < 4; i++) {
        int4 q = make_int4(base_excl + loc[i * 4 + 0], base_excl + loc[i * 4 + 1],
                           base_excl + loc[i * 4 + 2], base_excl + loc[i * 4 + 3]);
        rp[t * 4 + i] = q;
        op[t * 4 + i] = q;
    }
    if (t == 1023) g_rowptr[BN_TOT] = wsum[31];
}

// ---------------- place edges into CSR slots ------------------------------------
__global__ void place_kernel() {
    int e = blockIdx.x * blockDim.x + threadIdx.x;
    if (e >= ET) return;
    int d = g_dst[e];
    int slot = atomicAdd(&g_ofs[d], 1);
    g_csrc[slot] = g_src[e];
}

// ---------------- fp32 GEMM (128x128x16, 8x8 reg tile) + fused attdot -----------
// xt[16384,512] = x[16384,256] @ W[256,512], column-chunked by bx0 (1 chunk = 2 heads).
// Epilogue: fp16 store of xt + asrc/adst per (node, head) from fp32 accumulators.
#define TM 128
#define TN 128
#define BK 16
__global__ void gemm_kernel(const float* __restrict__ A, const float* __restrict__ Bw,
                            const float* __restrict__ att_src,
                            const float* __restrict__ att_dst, int bx0) {
    __shared__ float As[BK][TM];
    __shared__ float Bs[BK][TN];

    const int tid = threadIdx.x;
    const int bx  = bx0 + blockIdx.x;       // column block (0..3)
    const int by  = blockIdx.y;             // row block (0..127)

    const int tr = (tid >> 4) << 3;          // 0..120 step 8
    const int tc = (tid & 15) << 3;          // 0..120 step 8

    const int ar = tid >> 2;                 // 0..63
    const int ak = (tid & 3) << 2;           // 0,4,8,12
    const int br = tid >> 5;                 // 0..7
    const int bc = (tid & 31) << 2;          // 0..124

    float acc[8][8] = {};

    const float* Ap = A + (size_t)(by * TM + ar) * Cc + ak;
    const float* Bp = Bw + (size_t)br * F + bx * TN + bc;

    for (int k0 = 0; k0 < Cc; k0 += BK) {
        float4 a0 = *(const float4*)(Ap + k0);
        float4 a1 = *(const float4*)(Ap + (size_t)64 * Cc + k0);
        As[ak + 0][ar] = a0.x; As[ak + 1][ar] = a0.y;
        As[ak + 2][ar] = a0.z; As[ak + 3][ar] = a0.w;
        As[ak + 0][ar + 64] = a1.x; As[ak + 1][ar + 64] = a1.y;
        As[ak + 2][ar + 64] = a1.z; As[ak + 3][ar + 64] = a1.w;
        *(float4*)&Bs[br][bc]     = *(const float4*)(Bp + (size_t)k0 * F);
        *(float4*)&Bs[br + 8][bc] = *(const float4*)(Bp + (size_t)(k0 + 8) * F);
        __syncthreads();

#pragma unroll
        for (int k = 0; k < BK; k++) {
            float4 x0 = *(const float4*)&As[k][tr];
            float4 x1 = *(const float4*)&As[k][tr + 4];
            float4 y0 = *(const float4*)&Bs[k][tc];
            float4 y1 = *(const float4*)&Bs[k][tc + 4];
            float av[8] = {x0.x, x0.y, x0.z, x0.w, x1.x, x1.y, x1.z, x1.w};
            float bv[8] = {y0.x, y0.y, y0.z, y0.w, y1.x, y1.y, y1.z, y1.w};
#pragma unroll
            for (int i = 0; i < 8; i++)
#pragma unroll
                for (int j = 0; j < 8; j++)
                    acc[i][j] += av[i] * bv[j];
        }
        __syncthreads();
    }

    // store xt tile as fp16
#pragma unroll
    for (int i = 0; i < 8; i++) {
        size_t row = (size_t)(by * TM + tr + i);
        __half2 h4[4];
        h4[0] = __floats2half2_rn(acc[i][0], acc[i][1]);
        h4[1] = __floats2half2_rn(acc[i][2], acc[i][3]);
        h4[2] = __floats2half2_rn(acc[i][4], acc[i][5]);
        h4[3] = __floats2half2_rn(acc[i][6], acc[i][7]);
        *(uint4*)(g_xt + row * F + bx * TN + tc) = *(uint4*)h4;
    }

    // fused attdot (fp32 accumulators): this thread's 8 cols lie inside ONE head.
    {
        const int lane = tid & 31;
        const int h    = bx * 2 + (tc >> 6);
        const int chb  = tc & 63;
        const float* asv = att_src + h * CO + chb;
        const float* adv = att_dst + h * CO + chb;
        float as[8], ad[8];
#pragma unroll
        for (int j = 0; j < 8; j++) { as[j] = asv[j]; ad[j] = adv[j]; }

#pragma unroll
        for (int i = 0; i < 8; i++) {
            float s = 0.0f, d = 0.0f;
#pragma unroll
            for (int j = 0; j < 8; j++) {
                s += acc[i][j] * as[j];
                d += acc[i][j] * ad[j];
            }
#pragma unroll
            for (int o = 1; o <= 4; o <<= 1) {
                s += __shfl_xor_sync(0xffffffffu, s, o);
                d += __shfl_xor_sync(0xffffffffu, d, o);
            }
            if ((lane & 7) == 0) {
                int n = by * TM + tr + i;
                g_asrc[n * Hh + h] = s;
                g_adst[n * Hh + h] = d;
            }
        }
    }
}

// ---------------- fused softmax + weighted gather for a 2-head group ------------
// One block per dst node (64 threads = 2 warps); warp w handles head hbase+w.
// Alphas/src packed into per-warp smem; inner loop: 4 LDS.64 broadcasts +
// 4 independent half2 loads + 4 FFMA pairs into 4 accumulators (MLP=4).
// Zero-padded (alpha=0, src=0) entries make the unrolled loop guard-free.
__global__ void gather_kernel(float* __restrict__ out, const float* __restrict__ bias,
                              int hbase) {
    __shared__ unsigned long long sw[2][32];
    int n = blockIdx.x;
    int w = threadIdx.x >> 5;
    int h = hbase + w;
    int lane = threadIdx.x & 31;
    int start = g_rowptr[n];
    int end   = g_rowptr[n + 1];
    int deg   = end - start;

    float adstv = g_adst[n * Hh + h];
    const __half* xb = g_xt + h * CO + lane * 2;

    float2 acc0 = {0.f, 0.f}, acc1 = {0.f, 0.f}, acc2 = {0.f, 0.f}, acc3 = {0.f, 0.f};

    if (deg <= 32) {
        // softmax fully in registers: one logit + one expf per edge-head
        int s = 0;
        float l = -1e30f;
        if (lane < deg) {
            s = g_csrc[start + lane];
            float t = g_asrc[s * Hh + h] + adstv;
            l = (t > 0.0f) ? t : NEG * t;
        }
        float m = l;
#pragma unroll
        for (int o = 16; o; o >>= 1) m = fmaxf(m, __shfl_xor_sync(0xffffffffu, m, o));
        float wgt = (lane < deg) ? expf(l - m) : 0.0f;
        float sum = wgt;
#pragma unroll
        for (int o = 16; o; o >>= 1) sum += __shfl_xor_sync(0xffffffffu, sum, o);
        float a = wgt / (sum + 1e-16f);           // 0 for padding lanes

        sw[w][lane] = ((unsigned long long)(unsigned)s << 32) | __float_as_uint(a);
        __syncwarp();

        int dr = (deg + 3) & ~3;                  // <= 32
        for (int j = 0; j < dr; j += 4) {
            unsigned long long e0 = sw[w][j + 0];
            unsigned long long e1 = sw[w][j + 1];
            unsigned long long e2 = sw[w][j + 2];
            unsigned long long e3 = sw[w][j + 3];
            float a0 = __uint_as_float((unsigned)e0); int s0 = (int)(e0 >> 32);
            float a1 = __uint_as_float((unsigned)e1); int s1 = (int)(e1 >> 32);
            float a2 = __uint_as_float((unsigned)e2); int s2 = (int)(e2 >> 32);
            float a3 = __uint_as_float((unsigned)e3); int s3 = (int)(e3 >> 32);
            float2 v0 = __half22float2(*(const __half2*)(xb + (size_t)s0 * F));
            float2 v1 = __half22float2(*(const __half2*)(xb + (size_t)s1 * F));
            float2 v2 = __half22float2(*(const __half2*)(xb + (size_t)s2 * F));
            float2 v3 = __half22float2(*(const __half2*)(xb + (size_t)s3 * F));
            acc0.x += a0 * v0.x; acc0.y += a0 * v0.y;
            acc1.x += a1 * v1.x; acc1.y += a1 * v1.y;
            acc2.x += a2 * v2.x; acc2.y += a2 * v2.y;
            acc3.x += a3 * v3.x; acc3.y += a3 * v3.y;
        }
    } else {
        // general path (few nodes): two reduction passes, then chunked accumulation
        float m = -1e30f;
        for (int i = start + lane; i < end; i += 32) {
            int s = g_csrc[i];
            float t = g_asrc[s * Hh + h] + adstv;
            t = (t > 0.0f) ? t : NEG * t;
            m = fmaxf(m, t);
        }
#pragma unroll
        for (int o = 16; o; o >>= 1) m = fmaxf(m, __shfl_xor_sync(0xffffffffu, m, o));

        float sum = 0.0f;
        for (int i = start + lane; i < end; i += 32) {
            int s = g_csrc[i];
            float t = g_asrc[s * Hh + h] + adstv;
            t = (t > 0.0f) ? t : NEG * t;
            sum += expf(t - m);
        }
#pragma unroll
        for (int o = 16; o; o >>= 1) sum += __shfl_xor_sync(0xffffffffu, sum, o);
        float inv = 1.0f / (sum + 1e-16f);

        for (int base = start; base < end; base += 32) {
            int i = base + lane;
            int cnt = end - base;
            if (cnt > 32) cnt = 32;
            int sreg = 0;
            float areg = 0.0f;
            if (i < end) {
                sreg = g_csrc[i];
                float t = g_asrc[sreg * Hh + h] + adstv;
                t = (t > 0.0f) ? t : NEG * t;
                areg = expf(t - m) * inv;
            }
            __syncwarp();   // protect smem from previous chunk's readers
            sw[w][lane] = ((unsigned long long)(unsigned)sreg << 32) | __float_as_uint(areg);
            __syncwarp();

            int cr = (cnt + 3) & ~3;
            for (int j = 0; j < cr; j += 4) {
                unsigned long long e0 = sw[w][j + 0];
                unsigned long long e1 = sw[w][j + 1];
                unsigned long long e2 = sw[w][j + 2];
                unsigned long long e3 = sw[w][j + 3];
                float a0 = __uint_as_float((unsigned)e0); int s0 = (int)(e0 >> 32);
                float a1 = __uint_as_float((unsigned)e1); int s1 = (int)(e1 >> 32);
                float a2 = __uint_as_float((unsigned)e2); int s2 = (int)(e2 >> 32);
                float a3 = __uint_as_float((unsigned)e3); int s3 = (int)(e3 >> 32);
                float2 v0 = __half22float2(*(const __half2*)(xb + (size_t)s0 * F));
                float2 v1 = __half22float2(*(const __half2*)(xb + (size_t)s1 * F));
                float2 v2 = __half22float2(*(const __half2*)(xb + (size_t)s2 * F));
                float2 v3 = __half22float2(*(const __half2*)(xb + (size_t)s3 * F));
                acc0.x += a0 * v0.x; acc0.y += a0 * v0.y;
                acc1.x += a1 * v1.x; acc1.y += a1 * v1.y;
                acc2.x += a2 * v2.x; acc2.y += a2 * v2.y;
                acc3.x += a3 * v3.x; acc3.y += a3 * v3.y;
            }
        }
    }

    float2 acc = make_float2((acc0.x + acc1.x) + (acc2.x + acc3.x),
                             (acc0.y + acc1.y) + (acc2.y + acc3.y));

    int c = h * CO + lane * 2;
    float2 bv = *(const float2*)(bias + c);
    *(float2*)(out + (size_t)n * F + c) = make_float2(acc.x + bv.x, acc.y + bv.y);
}

// ---------------- launch: CSR build || 4-chunk GEMM, pipelined 2-head gathers ---
extern "C" void kernel_launch(void* const* d_in, const int* in_sizes, int n_in,
                              void* d_out, int out_size) {
    const float* x    = (const float*)d_in[0];
    const void*  ei   = d_in[1];
    const float* W    = (const float*)d_in[2];
    const float* asrc = (const float*)d_in[3];
    const float* adst = (const float*)d_in[4];
    const float* bias = (const float*)d_in[5];
    float* out = (float*)d_out;

    static cudaStream_t s2 = nullptr;
    static cudaEvent_t ev_fork = nullptr;
    static cudaEvent_t ev_g[4] = {nullptr, nullptr, nullptr, nullptr};
    if (s2 == nullptr) {
        cudaStreamCreateWithFlags(&s2, cudaStreamNonBlocking);
        cudaEventCreateWithFlags(&ev_fork, cudaEventDisableTiming);
        for (int c = 0; c < 4; c++) cudaEventCreateWithFlags(&ev_g[c], cudaEventDisableTiming);
    }

    cudaEventRecord(ev_fork, 0);
    cudaStreamWaitEvent(s2, ev_fork, 0);

    // GEMM chunks on s2: chunk c covers columns [128c, 128c+128) = heads 2c, 2c+1
    for (int c = 0; c < 4; c++) {
        gemm_kernel<<<dim3(1, BN_TOT / TM), 256, 0, s2>>>(x, W, asrc, adst, c);
        cudaEventRecord(ev_g[c], s2);
    }

    // CSR build on the capture stream (hidden under GEMM chunk 0)
    detect_zero_kernel<<<BN_TOT / 256, 256>>>((const unsigned*)ei);
    decode_count_kernel<<<(ET + 255) / 256, 256>>>(ei);
    scan_kernel<<<1, 1024>>>();
    place_kernel<<<(ET + 255) / 256, 256>>>();

    // pipelined gathers: gather c needs GEMM chunk c (and CSR, by program order)
    for (int c = 0; c < 4; c++) {
        cudaStreamWaitEvent(0, ev_g[c], 0);
        gather_kernel<<<BN_TOT, 64>>>(out, bias, 2 * c);
    }
}

// round 9
// speedup vs baseline: 1.1007x; 1.1007x over previous
#include <cuda_runtime.h>
#include <cuda_fp16.h>
#include <math.h>

// Problem constants
#define Bb      8
#define Nn      2048
#define Cc      256
#define Ee      32768
#define Hh      8
#define CO      64
#define BN_TOT  (Bb * Nn)          // 16384 nodes
#define F       (Hh * CO)          // 512 features
#define BE      (Bb * Ee)          // 262144 real edges
#define ET      (BE + BN_TOT)      // 278528 edges incl. self loops
#define NEG     0.2f

// ---------------- scratch (static device globals; no allocation) ----------------
__device__ __half g_xt[(size_t)BN_TOT * F];    // projected features, fp16, 16 MB
__device__ float  g_asrc[BN_TOT * Hh];         // per-node src attention dot (fp32)
__device__ float  g_adst[BN_TOT * Hh];         // per-node dst attention dot (fp32)
__device__ int    g_src[ET];
__device__ int    g_dst[ET];
__device__ int    g_cnt[BN_TOT];               // in-degree counts
__device__ int    g_rowptr[BN_TOT + 1];        // CSR row pointers (by dst)
__device__ int    g_ofs[BN_TOT];               // running offsets for place
__device__ int    g_csrc[ET];                  // CSR: src node per slot
__device__ int    g_is64;

// ---------------- detect edge dtype + zero counts (merged) ----------------------
__global__ void detect_zero_kernel(const unsigned* __restrict__ w) {
    int t = blockIdx.x * blockDim.x + threadIdx.x;
    if (t < BN_TOT) g_cnt[t] = 0;
    if (blockIdx.x == 0 && threadIdx.x < 32) {
        unsigned v = w[2 * threadIdx.x + 1];   // int64 => odd words zero
        unsigned all0 = __all_sync(0xffffffffu, v == 0u);
        if (threadIdx.x == 0) g_is64 = all0 ? 1 : 0;
    }
}

// ---------------- decode batched edges (+ self loops) and count in-degrees ------
__global__ void decode_count_kernel(const void* __restrict__ eiv) {
    int e = blockIdx.x * blockDim.x + threadIdx.x;
    if (e >= ET) return;
    int s, d;
    if (e < BE) {
        int k = e & (Ee - 1);
        int b = e >> 15;
        if (g_is64) {
            const long long* p = (const long long*)eiv;
            s = (int)p[k];
            d = (int)p[Ee + k];
        } else {
            const int* p = (const int*)eiv;
            s = p[k];
            d = p[Ee + k];
        }
        s += b * Nn;
        d += b * Nn;
    } else {
        s = d = e - BE;
    }
    g_src[e] = s;
    g_dst[e] = d;
    atomicAdd(&g_cnt[d], 1);
}

// ---------------- single-block exclusive scan over 16384 counts -----------------
__global__ void scan_kernel() {
    __shared__ int wsum[32];
    const int t = threadIdx.x;
    const int lane = t & 31;
    const int w = t >> 5;

    const int4* cin = (const int4*)g_cnt;
    int4 c0 = cin[t * 4 + 0];
    int4 c1 = cin[t * 4 + 1];
    int4 c2 = cin[t * 4 + 2];
    int4 c3 = cin[t * 4 + 3];
    int v[16] = {c0.x, c0.y, c0.z, c0.w, c1.x, c1.y, c1.z, c1.w,
                 c2.x, c2.y, c2.z, c2.w, c3.x, c3.y, c3.z, c3.w};

    int loc[16];
    int s = 0;
#pragma unroll
    for (int i = 0; i < 16; i++) { loc[i] = s; s += v[i]; }

    int inc = s;
#pragma unroll
    for (int o = 1; o < 32; o <<= 1) {
        int u = __shfl_up_sync(0xffffffffu, inc, o);
        if (lane >= o) inc += u;
    }
    if (lane == 31) wsum[w] = inc;
    __syncthreads();
    if (w == 0) {
        int x = wsum[lane];
#pragma unroll
        for (int o = 1; o < 32; o <<= 1) {
            int u = __shfl_up_sync(0xffffffffu, x, o);
            if (lane >= o) x += u;
        }
        wsum[lane] = x;
    }
    __syncthreads();

    int base_excl = (inc - s) + (w > 0 ? wsum[w - 1] : 0);

    int4* rp = (int4*)g_rowptr;
    int4* op = (int4*)g_ofs;
#pragma unroll
    for (int i = 0; i < 4; i++) {
        int4 q = make_int4(base_excl + loc[i * 4 + 0], base_excl + loc[i * 4 + 1],
                           base_excl + loc[i * 4 + 2], base_excl + loc[i * 4 + 3]);
        rp[t * 4 + i] = q;
        op[t * 4 + i] = q;
    }
    if (t == 1023) g_rowptr[BN_TOT] = wsum[31];
}

// ---------------- place edges into CSR slots ------------------------------------
__global__ void place_kernel() {
    int e = blockIdx.x * blockDim.x + threadIdx.x;
    if (e >= ET) return;
    int d = g_dst[e];
    int slot = atomicAdd(&g_ofs[d], 1);
    g_csrc[slot] = g_src[e];
}

// ---------------- fp32 GEMM (128x128x16, 8x8 reg tile) + fused attdot -----------
// xt[16384,512] = x[16384,256] @ W[256,512], column-chunked by bx0 (chunk = 4 heads,
// grid dim3(2,128) = 256 blocks; with 2 CTAs/SM that's one fully-resident wave).
#define TM 128
#define TN 128
#define BK 16
__global__ void __launch_bounds__(256, 2)
gemm_kernel(const float* __restrict__ A, const float* __restrict__ Bw,
            const float* __restrict__ att_src,
            const float* __restrict__ att_dst, int bx0) {
    __shared__ float As[BK][TM];
    __shared__ float Bs[BK][TN];

    const int tid = threadIdx.x;
    const int bx  = bx0 + blockIdx.x;       // column block (0..3)
    const int by  = blockIdx.y;             // row block (0..127)

    const int tr = (tid >> 4) << 3;          // 0..120 step 8
    const int tc = (tid & 15) << 3;          // 0..120 step 8

    const int ar = tid >> 2;                 // 0..63
    const int ak = (tid & 3) << 2;           // 0,4,8,12
    const int br = tid >> 5;                 // 0..7
    const int bc = (tid & 31) << 2;          // 0..124

    float acc[8][8] = {};

    const float* Ap = A + (size_t)(by * TM + ar) * Cc + ak;
    const float* Bp = Bw + (size_t)br * F + bx * TN + bc;

    for (int k0 = 0; k0 < Cc; k0 += BK) {
        float4 a0 = *(const float4*)(Ap + k0);
        float4 a1 = *(const float4*)(Ap + (size_t)64 * Cc + k0);
        As[ak + 0][ar] = a0.x; As[ak + 1][ar] = a0.y;
        As[ak + 2][ar] = a0.z; As[ak + 3][ar] = a0.w;
        As[ak + 0][ar + 64] = a1.x; As[ak + 1][ar + 64] = a1.y;
        As[ak + 2][ar + 64] = a1.z; As[ak + 3][ar + 64] = a1.w;
        *(float4*)&Bs[br][bc]     = *(const float4*)(Bp + (size_t)k0 * F);
        *(float4*)&Bs[br + 8][bc] = *(const float4*)(Bp + (size_t)(k0 + 8) * F);
        __syncthreads();

#pragma unroll
        for (int k = 0; k < BK; k++) {
            float4 x0 = *(const float4*)&As[k][tr];
            float4 x1 = *(const float4*)&As[k][tr + 4];
            float4 y0 = *(const float4*)&Bs[k][tc];
            float4 y1 = *(const float4*)&Bs[k][tc + 4];
            float av[8] = {x0.x, x0.y, x0.z, x0.w, x1.x, x1.y, x1.z, x1.w};
            float bv[8] = {y0.x, y0.y, y0.z, y0.w, y1.x, y1.y, y1.z, y1.w};
#pragma unroll
            for (int i = 0; i < 8; i++)
#pragma unroll
                for (int j = 0; j < 8; j++)
                    acc[i][j] += av[i] * bv[j];
        }
        __syncthreads();
    }

    // store xt tile as fp16
#pragma unroll
    for (int i = 0; i < 8; i++) {
        size_t row = (size_t)(by * TM + tr + i);
        __half2 h4[4];
        h4[0] = __floats2half2_rn(acc[i][0], acc[i][1]);
        h4[1] = __floats2half2_rn(acc[i][2], acc[i][3]);
        h4[2] = __floats2half2_rn(acc[i][4], acc[i][5]);
        h4[3] = __floats2half2_rn(acc[i][6], acc[i][7]);
        *(uint4*)(g_xt + row * F + bx * TN + tc) = *(uint4*)h4;
    }

    // fused attdot (fp32 accumulators): this thread's 8 cols lie inside ONE head.
    {
        const int lane = tid & 31;
        const int h    = bx * 2 + (tc >> 6);
        const int chb  = tc & 63;
        const float* asv = att_src + h * CO + chb;
        const float* adv = att_dst + h * CO + chb;
        float as[8], ad[8];
#pragma unroll
        for (int j = 0; j < 8; j++) { as[j] = asv[j]; ad[j] = adv[j]; }

#pragma unroll
        for (int i = 0; i < 8; i++) {
            float s = 0.0f, d = 0.0f;
#pragma unroll
            for (int j = 0; j < 8; j++) {
                s += acc[i][j] * as[j];
                d += acc[i][j] * ad[j];
            }
#pragma unroll
            for (int o = 1; o <= 4; o <<= 1) {
                s += __shfl_xor_sync(0xffffffffu, s, o);
                d += __shfl_xor_sync(0xffffffffu, d, o);
            }
            if ((lane & 7) == 0) {
                int n = by * TM + tr + i;
                g_asrc[n * Hh + h] = s;
                g_adst[n * Hh + h] = d;
            }
        }
    }
}

// ---------------- fused softmax + weighted gather for a 4-head group ------------
// One block per dst node (128 threads = 4 warps); warp w handles head hbase+w.
// Alphas/src packed into per-warp smem; inner loop: 4 LDS.64 broadcasts +
// 4 independent half2 loads + 4 FFMA pairs into 4 accumulators (MLP=4).
__global__ void gather_kernel(float* __restrict__ out, const float* __restrict__ bias,
                              int hbase) {
    __shared__ unsigned long long sw[4][32];
    int n = blockIdx.x;
    int w = threadIdx.x >> 5;
    int h = hbase + w;
    int lane = threadIdx.x & 31;
    int start = g_rowptr[n];
    int end   = g_rowptr[n + 1];
    int deg   = end - start;

    float adstv = g_adst[n * Hh + h];
    const __half* xb = g_xt + h * CO + lane * 2;

    float2 acc0 = {0.f, 0.f}, acc1 = {0.f, 0.f}, acc2 = {0.f, 0.f}, acc3 = {0.f, 0.f};

    if (deg <= 32) {
        // softmax fully in registers: one logit + one expf per edge-head
        int s = 0;
        float l = -1e30f;
        if (lane < deg) {
            s = g_csrc[start + lane];
            float t = g_asrc[s * Hh + h] + adstv;
            l = (t > 0.0f) ? t : NEG * t;
        }
        float m = l;
#pragma unroll
        for (int o = 16; o; o >>= 1) m = fmaxf(m, __shfl_xor_sync(0xffffffffu, m, o));
        float wgt = (lane < deg) ? expf(l - m) : 0.0f;
        float sum = wgt;
#pragma unroll
        for (int o = 16; o; o >>= 1) sum += __shfl_xor_sync(0xffffffffu, sum, o);
        float a = wgt / (sum + 1e-16f);           // 0 for padding lanes

        sw[w][lane] = ((unsigned long long)(unsigned)s << 32) | __float_as_uint(a);
        __syncwarp();

        int dr = (deg + 3) & ~3;                  // <= 32
        for (int j = 0; j < dr; j += 4) {
            unsigned long long e0 = sw[w][j + 0];
            unsigned long long e1 = sw[w][j + 1];
            unsigned long long e2 = sw[w][j + 2];
            unsigned long long e3 = sw[w][j + 3];
            float a0 = __uint_as_float((unsigned)e0); int s0 = (int)(e0 >> 32);
            float a1 = __uint_as_float((unsigned)e1); int s1 = (int)(e1 >> 32);
            float a2 = __uint_as_float((unsigned)e2); int s2 = (int)(e2 >> 32);
            float a3 = __uint_as_float((unsigned)e3); int s3 = (int)(e3 >> 32);
            float2 v0 = __half22float2(*(const __half2*)(xb + (size_t)s0 * F));
            float2 v1 = __half22float2(*(const __half2*)(xb + (size_t)s1 * F));
            float2 v2 = __half22float2(*(const __half2*)(xb + (size_t)s2 * F));
            float2 v3 = __half22float2(*(const __half2*)(xb + (size_t)s3 * F));
            acc0.x += a0 * v0.x; acc0.y += a0 * v0.y;
            acc1.x += a1 * v1.x; acc1.y += a1 * v1.y;
            acc2.x += a2 * v2.x; acc2.y += a2 * v2.y;
            acc3.x += a3 * v3.x; acc3.y += a3 * v3.y;
        }
    } else {
        // general path (few nodes): two reduction passes, then chunked accumulation
        float m = -1e30f;
        for (int i = start + lane; i < end; i += 32) {
            int s = g_csrc[i];
            float t = g_asrc[s * Hh + h] + adstv;
            t = (t > 0.0f) ? t : NEG * t;
            m = fmaxf(m, t);
        }
#pragma unroll
        for (int o = 16; o; o >>= 1) m = fmaxf(m, __shfl_xor_sync(0xffffffffu, m, o));

        float sum = 0.0f;
        for (int i = start + lane; i < end; i += 32) {
            int s = g_csrc[i];
            float t = g_asrc[s * Hh + h] + adstv;
            t = (t > 0.0f) ? t : NEG * t;
            sum += expf(t - m);
        }
#pragma unroll
        for (int o = 16; o; o >>= 1) sum += __shfl_xor_sync(0xffffffffu, sum, o);
        float inv = 1.0f / (sum + 1e-16f);

        for (int base = start; base < end; base += 32) {
            int i = base + lane;
            int cnt = end - base;
            if (cnt > 32) cnt = 32;
            int sreg = 0;
            float areg = 0.0f;
            if (i < end) {
                sreg = g_csrc[i];
                float t = g_asrc[sreg * Hh + h] + adstv;
                t = (t > 0.0f) ? t : NEG * t;
                areg = expf(t - m) * inv;
            }
            __syncwarp();   // protect smem from previous chunk's readers
            sw[w][lane] = ((unsigned long long)(unsigned)sreg << 32) | __float_as_uint(areg);
            __syncwarp();

            int cr = (cnt + 3) & ~3;
            for (int j = 0; j < cr; j += 4) {
                unsigned long long e0 = sw[w][j + 0];
                unsigned long long e1 = sw[w][j + 1];
                unsigned long long e2 = sw[w][j + 2];
                unsigned long long e3 = sw[w][j + 3];
                float a0 = __uint_as_float((unsigned)e0); int s0 = (int)(e0 >> 32);
                float a1 = __uint_as_float((unsigned)e1); int s1 = (int)(e1 >> 32);
                float a2 = __uint_as_float((unsigned)e2); int s2 = (int)(e2 >> 32);
                float a3 = __uint_as_float((unsigned)e3); int s3 = (int)(e3 >> 32);
                float2 v0 = __half22float2(*(const __half2*)(xb + (size_t)s0 * F));
                float2 v1 = __half22float2(*(const __half2*)(xb + (size_t)s1 * F));
                float2 v2 = __half22float2(*(const __half2*)(xb + (size_t)s2 * F));
                float2 v3 = __half22float2(*(const __half2*)(xb + (size_t)s3 * F));
                acc0.x += a0 * v0.x; acc0.y += a0 * v0.y;
                acc1.x += a1 * v1.x; acc1.y += a1 * v1.y;
                acc2.x += a2 * v2.x; acc2.y += a2 * v2.y;
                acc3.x += a3 * v3.x; acc3.y += a3 * v3.y;
            }
        }
    }

    float2 acc = make_float2((acc0.x + acc1.x) + (acc2.x + acc3.x),
                             (acc0.y + acc1.y) + (acc2.y + acc3.y));

    int c = h * CO + lane * 2;
    float2 bv = *(const float2*)(bias + c);
    *(float2*)(out + (size_t)n * F + c) = make_float2(acc.x + bv.x, acc.y + bv.y);
}

// ---------------- launch: CSR build || 2-chunk GEMM, pipelined gathers ----------
extern "C" void kernel_launch(void* const* d_in, const int* in_sizes, int n_in,
                              void* d_out, int out_size) {
    const float* x    = (const float*)d_in[0];
    const void*  ei   = d_in[1];
    const float* W    = (const float*)d_in[2];
    const float* asrc = (const float*)d_in[3];
    const float* adst = (const float*)d_in[4];
    const float* bias = (const float*)d_in[5];
    float* out = (float*)d_out;

    static cudaStream_t s2 = nullptr;
    static cudaEvent_t ev_fork = nullptr, ev_g0 = nullptr, ev_g1 = nullptr;
    if (s2 == nullptr) {
        cudaStreamCreateWithFlags(&s2, cudaStreamNonBlocking);
        cudaEventCreateWithFlags(&ev_fork, cudaEventDisableTiming);
        cudaEventCreateWithFlags(&ev_g0, cudaEventDisableTiming);
        cudaEventCreateWithFlags(&ev_g1, cudaEventDisableTiming);
    }

    cudaEventRecord(ev_fork, 0);
    cudaStreamWaitEvent(s2, ev_fork, 0);

    // GEMM chunk 0: columns 0..255 = heads 0..3 (256 blocks = full wave @ 2 CTA/SM)
    gemm_kernel<<<dim3(2, BN_TOT / TM), 256, 0, s2>>>(x, W, asrc, adst, 0);
    cudaEventRecord(ev_g0, s2);
    // GEMM chunk 1: columns 256..511 = heads 4..7
    gemm_kernel<<<dim3(2, BN_TOT / TM), 256, 0, s2>>>(x, W, asrc, adst, 2);
    cudaEventRecord(ev_g1, s2);

    // CSR build on the capture stream (hidden under GEMM chunk 0)
    detect_zero_kernel<<<BN_TOT / 256, 256>>>((const unsigned*)ei);
    decode_count_kernel<<<(ET + 255) / 256, 256>>>(ei);
    scan_kernel<<<1, 1024>>>();
    place_kernel<<<(ET + 255) / 256, 256>>>();

    // gather heads 0..3 overlaps GEMM chunk 1
    cudaStreamWaitEvent(0, ev_g0, 0);
    gather_kernel<<<BN_TOT, 128>>>(out, bias, 0);
    cudaStreamWaitEvent(0, ev_g1, 0);
    gather_kernel<<<BN_TOT, 128>>>(out, bias, 4);
}

// round 10
// speedup vs baseline: 1.9901x; 1.8080x over previous
#include <cuda_runtime.h>
#include <cuda_fp16.h>
#include <math.h>

// Problem constants
#define Bb      8
#define Nn      2048
#define Cc      256
#define Ee      32768
#define Hh      8
#define CO      64
#define BN_TOT  (Bb * Nn)          // 16384 nodes
#define F       (Hh * CO)          // 512 features
#define BE      (Bb * Ee)          // 262144 real edges
#define ET      (BE + BN_TOT)      // 278528 edges incl. self loops
#define NEG     0.2f

// ---------------- scratch (static device globals; no allocation) ----------------
__device__ __half g_xt[(size_t)BN_TOT * F];    // projected features, fp16, 16 MB
__device__ float  g_asrc[BN_TOT * Hh];         // per-node src attention dot (fp32)
__device__ float  g_adst[BN_TOT * Hh];         // per-node dst attention dot (fp32)
__device__ int    g_cnt[BN_TOT];               // in-degree counts
__device__ int    g_rowptr[BN_TOT + 1];        // CSR row pointers (by dst)
__device__ int    g_ofs[BN_TOT];               // running offsets for place
__device__ int    g_srcb[ET];                  // decoded src (batched)
__device__ int    g_dstb[ET];                  // decoded dst (batched)
__device__ int    g_csrc[ET];                  // CSR: src node per slot

// ---------------- decode batched edges (+ self loops), count in-degrees ---------
// Edge dtype (int64 vs silently-int32) detected per-warp: if int64, all odd
// 32-bit words of the buffer are zero high-halves. All lanes converged here.
__global__ void decode_count_kernel(const void* __restrict__ eiv) {
    const unsigned* w = (const unsigned*)eiv;
    unsigned v = w[2 * (threadIdx.x & 31) + 1];
    int is64 = __all_sync(0xffffffffu, v == 0u);

    int e = blockIdx.x * blockDim.x + threadIdx.x;
    if (e >= ET) return;
    int s, d;
    if (e < BE) {
        int k = e & (Ee - 1);
        int b = e >> 15;
        if (is64) {
            const long long* p = (const long long*)eiv;
            s = (int)p[k];
            d = (int)p[Ee + k];
        } else {
            const int* p = (const int*)eiv;
            s = p[k];
            d = p[Ee + k];
        }
        s += b * Nn;
        d += b * Nn;
    } else {
        s = d = e - BE;
    }
    g_srcb[e] = s;
    g_dstb[e] = d;
    atomicAdd(&g_cnt[d], 1);
}

// ---------------- single-block exclusive scan over 16384 counts -----------------
__global__ void scan_kernel() {
    __shared__ int wsum[32];
    const int t = threadIdx.x;
    const int lane = t & 31;
    const int w = t >> 5;

    const int4* cin = (const int4*)g_cnt;
    int4 c0 = cin[t * 4 + 0];
    int4 c1 = cin[t * 4 + 1];
    int4 c2 = cin[t * 4 + 2];
    int4 c3 = cin[t * 4 + 3];
    int v[16] = {c0.x, c0.y, c0.z, c0.w, c1.x, c1.y, c1.z, c1.w,
                 c2.x, c2.y, c2.z, c2.w, c3.x, c3.y, c3.z, c3.w};

    int loc[16];
    int s = 0;
#pragma unroll
    for (int i = 0; i < 16; i++) { loc[i] = s; s += v[i]; }

    int inc = s;
#pragma unroll
    for (int o = 1; o < 32; o <<= 1) {
        int u = __shfl_up_sync(0xffffffffu, inc, o);
        if (lane >= o) inc += u;
    }
    if (lane == 31) wsum[w] = inc;
    __syncthreads();
    if (w == 0) {
        int x = wsum[lane];
#pragma unroll
        for (int o = 1; o < 32; o <<= 1) {
            int u = __shfl_up_sync(0xffffffffu, x, o);
            if (lane >= o) x += u;
        }
        wsum[lane] = x;
    }
    __syncthreads();

    int base_excl = (inc - s) + (w > 0 ? wsum[w - 1] : 0);

    int4* rp = (int4*)g_rowptr;
    int4* op = (int4*)g_ofs;
#pragma unroll
    for (int i = 0; i < 4; i++) {
        int4 q = make_int4(base_excl + loc[i * 4 + 0], base_excl + loc[i * 4 + 1],
                           base_excl + loc[i * 4 + 2], base_excl + loc[i * 4 + 3]);
        rp[t * 4 + i] = q;
        op[t * 4 + i] = q;
    }
    if (t == 1023) g_rowptr[BN_TOT] = wsum[31];
}

// ---------------- place edges into CSR slots ------------------------------------
__global__ void place_kernel() {
    int e = blockIdx.x * blockDim.x + threadIdx.x;
    if (e >= ET) return;
    int d = g_dstb[e];
    int slot = atomicAdd(&g_ofs[d], 1);
    g_csrc[slot] = g_srcb[e];
}

// ---------------- fp16 tensor-core GEMM (mma.sync m16n8k16, fp32 acc) -----------
// xt[16384,512] = x[16384,256] @ W[256,512], column-chunked by bx0 (chunk = 4 heads).
// 128x128 block tile, BK=32 (fp16), 256 threads = 8 warps in 4x2; warp tile 32x64.
// Smem: A as [m][k] halves (pad 40 -> banks 20*qr+qc, conflict-free);
//       B as k-pair-packed half2 words [k2][n] (pad 136 -> banks 8*qc+qr, c-free).
// Epilogue: fp16 xt store + fused attdot from fp32 accumulators.
#define BKH 32

#define MMA_F16(d, a, b)                                                          \
    asm volatile("mma.sync.aligned.m16n8k16.row.col.f32.f16.f16.f32 "             \
                 "{%0,%1,%2,%3}, {%4,%5,%6,%7}, {%8,%9}, {%0,%1,%2,%3};"          \
                 : "+f"(d[0]), "+f"(d[1]), "+f"(d[2]), "+f"(d[3])                  \
                 : "r"(a[0]), "r"(a[1]), "r"(a[2]), "r"(a[3]), "r"(b[0]), "r"(b[1]))

__global__ void __launch_bounds__(256, 2)
gemm_kernel(const float* __restrict__ A, const float* __restrict__ Bw,
            const float* __restrict__ att_src,
            const float* __restrict__ att_dst, int bx0) {
    __shared__ __half   As[128][40];     // [m][k] fp16, 10.0 KB
    __shared__ unsigned Bp[16][136];     // [k2][n] half2{k even, k odd}, 8.5 KB

    const int tid  = threadIdx.x;
    const int lane = tid & 31;
    const int wid  = tid >> 5;
    const int wr   = wid >> 1;           // 0..3
    const int wc   = wid & 1;            // 0..1
    const int bx   = bx0 + blockIdx.x;   // 0..3
    const int by   = blockIdx.y;         // 0..127
    const int qr   = lane >> 2;          // 0..7 (groupID)
    const int qc   = lane & 3;           // 0..3 (threadInGroup)

    float acc[2][8][4];
#pragma unroll
    for (int i = 0; i < 2; i++)
#pragma unroll
        for (int j = 0; j < 8; j++)
#pragma unroll
            for (int k = 0; k < 4; k++) acc[i][j][k] = 0.0f;

    for (int k0 = 0; k0 < Cc; k0 += BKH) {
        // A tile 128x32: load fp32, convert, store [m][k]
#pragma unroll
        for (int i = 0; i < 4; i++) {
            int idx = tid + i * 256;
            int r  = idx >> 3;               // 0..127
            int c4 = (idx & 7) << 2;         // 0..28
            float4 v = *(const float4*)(A + (size_t)(by * 128 + r) * Cc + k0 + c4);
            *(__half2*)&As[r][c4]     = __floats2half2_rn(v.x, v.y);
            *(__half2*)&As[r][c4 + 2] = __floats2half2_rn(v.z, v.w);
        }
        // B tile 32x128: load even/odd k rows, pack half2{k_even, k_odd} per n
#pragma unroll
        for (int i = 0; i < 2; i++) {
            int idx = tid + i * 256;
            int k2 = idx >> 5;               // 0..15
            int n4 = (idx & 31) << 2;        // 0..124
            const float* bp = Bw + (size_t)(k0 + 2 * k2) * F + bx * 128 + n4;
            float4 ev = *(const float4*)(bp);
            float4 ov = *(const float4*)(bp + F);
            __half2* dst = (__half2*)&Bp[k2][n4];
            dst[0] = __floats2half2_rn(ev.x, ov.x);
            dst[1] = __floats2half2_rn(ev.y, ov.y);
            dst[2] = __floats2half2_rn(ev.z, ov.z);
            dst[3] = __floats2half2_rn(ev.w, ov.w);
        }
        __syncthreads();

#pragma unroll
        for (int ks = 0; ks < 2; ks++) {     // two k16 steps per BK=32
            unsigned a[2][4];
            const int kk = ks * 16 + 2 * qc;
#pragma unroll
            for (int mt = 0; mt < 2; mt++) {
                int rm = wr * 32 + mt * 16 + qr;
                a[mt][0] = *(const unsigned*)&As[rm][kk];
                a[mt][1] = *(const unsigned*)&As[rm + 8][kk];
                a[mt][2] = *(const unsigned*)&As[rm][kk + 8];
                a[mt][3] = *(const unsigned*)&As[rm + 8][kk + 8];
            }
            unsigned b[8][2];
            const int kb = ks * 8 + qc;
#pragma unroll
            for (int nt = 0; nt < 8; nt++) {
                int col = wc * 64 + nt * 8 + qr;
                b[nt][0] = Bp[kb][col];
                b[nt][1] = Bp[kb + 4][col];
            }
#pragma unroll
            for (int mt = 0; mt < 2; mt++)
#pragma unroll
                for (int nt = 0; nt < 8; nt++)
                    MMA_F16(acc[mt][nt], a[mt], b[nt]);
        }
        __syncthreads();
    }

    // ---- epilogue: fp16 xt store ----
    // c0,c1 = (row qr, cols 2qc, 2qc+1); c2,c3 = (row qr+8, same cols)
#pragma unroll
    for (int mt = 0; mt < 2; mt++) {
        int r = by * 128 + wr * 32 + mt * 16 + qr;
#pragma unroll
        for (int nt = 0; nt < 8; nt++) {
            int c = bx * 128 + wc * 64 + nt * 8 + 2 * qc;
            *(__half2*)(g_xt + (size_t)r * F + c) =
                __floats2half2_rn(acc[mt][nt][0], acc[mt][nt][1]);
            *(__half2*)(g_xt + (size_t)(r + 8) * F + c) =
                __floats2half2_rn(acc[mt][nt][2], acc[mt][nt][3]);
        }
    }

    // ---- fused attdot (fp32 accumulators): head h = bx*2 + wc ----
    {
        const int h = bx * 2 + wc;
        const float* asv = att_src + h * CO;
        const float* adv = att_dst + h * CO;
        float s_att[16], d_att[16];
#pragma unroll
        for (int nt = 0; nt < 8; nt++) {
            int c = nt * 8 + 2 * qc;
            s_att[2 * nt]     = asv[c];
            s_att[2 * nt + 1] = asv[c + 1];
            d_att[2 * nt]     = adv[c];
            d_att[2 * nt + 1] = adv[c + 1];
        }
#pragma unroll
        for (int mt = 0; mt < 2; mt++) {
            float s0 = 0.f, d0 = 0.f, s1 = 0.f, d1 = 0.f;
#pragma unroll
            for (int nt = 0; nt < 8; nt++) {
                s0 += acc[mt][nt][0] * s_att[2 * nt] + acc[mt][nt][1] * s_att[2 * nt + 1];
                d0 += acc[mt][nt][0] * d_att[2 * nt] + acc[mt][nt][1] * d_att[2 * nt + 1];
                s1 += acc[mt][nt][2] * s_att[2 * nt] + acc[mt][nt][3] * s_att[2 * nt + 1];
                d1 += acc[mt][nt][2] * d_att[2 * nt] + acc[mt][nt][3] * d_att[2 * nt + 1];
            }
#pragma unroll
            for (int o = 1; o <= 2; o <<= 1) {       // reduce over qc (lane bits 0,1)
                s0 += __shfl_xor_sync(0xffffffffu, s0, o);
                d0 += __shfl_xor_sync(0xffffffffu, d0, o);
                s1 += __shfl_xor_sync(0xffffffffu, s1, o);
                d1 += __shfl_xor_sync(0xffffffffu, d1, o);
            }
            if (qc == 0) {
                int n0 = by * 128 + wr * 32 + mt * 16 + qr;
                g_asrc[n0 * Hh + h] = s0;
                g_adst[n0 * Hh + h] = d0;
                g_asrc[(n0 + 8) * Hh + h] = s1;
                g_adst[(n0 + 8) * Hh + h] = d1;
            }
        }
    }
}

// ---------------- fused softmax + weighted gather for a 4-head group ------------
// (exact R7 version — proven best) One block per dst node; one warp per head.
__global__ void gather_kernel(float* __restrict__ out, const float* __restrict__ bias,
                              int hbase) {
    int n = blockIdx.x;
    int h = hbase + (threadIdx.x >> 5);
    int lane = threadIdx.x & 31;
    int start = g_rowptr[n];
    int end   = g_rowptr[n + 1];
    int deg   = end - start;

    float adstv = g_adst[n * Hh + h];
    const __half* xb = g_xt + h * CO + lane * 2;

    float2 acc = make_float2(0.0f, 0.0f);

    if (deg <= 32) {
        int s = 0;
        float l = -1e30f;
        if (lane < deg) {
            s = g_csrc[start + lane];
            float t = g_asrc[s * Hh + h] + adstv;
            l = (t > 0.0f) ? t : NEG * t;
        }
        float m = l;
#pragma unroll
        for (int o = 16; o; o >>= 1) m = fmaxf(m, __shfl_xor_sync(0xffffffffu, m, o));
        float wgt = (lane < deg) ? expf(l - m) : 0.0f;
        float sum = wgt;
#pragma unroll
        for (int o = 16; o; o >>= 1) sum += __shfl_xor_sync(0xffffffffu, sum, o);
        float a = wgt / (sum + 1e-16f);

        for (int j = 0; j < deg; j++) {
            float aj = __shfl_sync(0xffffffffu, a, j);
            int   sj = __shfl_sync(0xffffffffu, s, j);
            float2 v = __half22float2(*(const __half2*)(xb + (size_t)sj * F));
            acc.x += aj * v.x;
            acc.y += aj * v.y;
        }
    } else {
        float m = -1e30f;
        for (int i = start + lane; i < end; i += 32) {
            int s = g_csrc[i];
            float t = g_asrc[s * Hh + h] + adstv;
            t = (t > 0.0f) ? t : NEG * t;
            m = fmaxf(m, t);
        }
#pragma unroll
        for (int o = 16; o; o >>= 1) m = fmaxf(m, __shfl_xor_sync(0xffffffffu, m, o));

        float sum = 0.0f;
        for (int i = start + lane; i < end; i += 32) {
            int s = g_csrc[i];
            float t = g_asrc[s * Hh + h] + adstv;
            t = (t > 0.0f) ? t : NEG * t;
            sum += expf(t - m);
        }
#pragma unroll
        for (int o = 16; o; o >>= 1) sum += __shfl_xor_sync(0xffffffffu, sum, o);
        float inv = 1.0f / (sum + 1e-16f);

        for (int base = start; base < end; base += 32) {
            int i = base + lane;
            int sreg = 0;
            float areg = 0.0f;
            if (i < end) {
                sreg = g_csrc[i];
                float t = g_asrc[sreg * Hh + h] + adstv;
                t = (t > 0.0f) ? t : NEG * t;
                areg = expf(t - m) * inv;
            }
            int cnt = end - base;
            if (cnt > 32) cnt = 32;
            for (int j = 0; j < cnt; j++) {
                float aj = __shfl_sync(0xffffffffu, areg, j);
                int   sj = __shfl_sync(0xffffffffu, sreg, j);
                float2 v = __half22float2(*(const __half2*)(xb + (size_t)sj * F));
                acc.x += aj * v.x;
                acc.y += aj * v.y;
            }
        }
    }

    int c = h * CO + lane * 2;
    float2 bv = *(const float2*)(bias + c);
    *(float2*)(out + (size_t)n * F + c) = make_float2(acc.x + bv.x, acc.y + bv.y);
}

// ---------------- launch: CSR build || 2-chunk GEMM, pipelined gathers ----------
extern "C" void kernel_launch(void* const* d_in, const int* in_sizes, int n_in,
                              void* d_out, int out_size) {
    const float* x    = (const float*)d_in[0];
    const void*  ei   = d_in[1];
    const float* W    = (const float*)d_in[2];
    const float* asrc = (const float*)d_in[3];
    const float* adst = (const float*)d_in[4];
    const float* bias = (const float*)d_in[5];
    float* out = (float*)d_out;

    static cudaStream_t s2 = nullptr;
    static cudaEvent_t ev_fork = nullptr, ev_g0 = nullptr, ev_g1 = nullptr;
    static void* cnt_ptr = nullptr;
    if (s2 == nullptr) {
        cudaStreamCreateWithFlags(&s2, cudaStreamNonBlocking);
        cudaEventCreateWithFlags(&ev_fork, cudaEventDisableTiming);
        cudaEventCreateWithFlags(&ev_g0, cudaEventDisableTiming);
        cudaEventCreateWithFlags(&ev_g1, cudaEventDisableTiming);
        cudaGetSymbolAddress(&cnt_ptr, g_cnt);
    }

    cudaEventRecord(ev_fork, 0);
    cudaStreamWaitEvent(s2, ev_fork, 0);

    // GEMM chunk 0: columns 0..255 = heads 0..3 (256 blocks, 2 CTA/SM)
    gemm_kernel<<<dim3(2, BN_TOT / 128), 256, 0, s2>>>(x, W, asrc, adst, 0);
    cudaEventRecord(ev_g0, s2);
    // GEMM chunk 1: columns 256..511 = heads 4..7
    gemm_kernel<<<dim3(2, BN_TOT / 128), 256, 0, s2>>>(x, W, asrc, adst, 2);
    cudaEventRecord(ev_g1, s2);

    // CSR build on the capture stream
    cudaMemsetAsync(cnt_ptr, 0, BN_TOT * sizeof(int), 0);
    decode_count_kernel<<<(ET + 255) / 256, 256>>>(ei);
    scan_kernel<<<1, 1024>>>();
    place_kernel<<<(ET + 255) / 256, 256>>>();

    // gather heads 0..3 overlaps GEMM chunk 1
    cudaStreamWaitEvent(0, ev_g0, 0);
    gather_kernel<<<BN_TOT, 128>>>(out, bias, 0);
    cudaStreamWaitEvent(0, ev_g1, 0);
    gather_kernel<<<BN_TOT, 128>>>(out, bias, 4);
}

// round 11
// speedup vs baseline: 2.0988x; 1.0547x over previous
#include <cuda_runtime.h>
#include <cuda_fp16.h>
#include <math.h>

// Problem constants
#define Bb      8
#define Nn      2048
#define Cc      256
#define Ee      32768
#define Hh      8
#define CO      64
#define BN_TOT  (Bb * Nn)          // 16384 nodes
#define F       (Hh * CO)          // 512 features
#define BE      (Bb * Ee)          // 262144 real edges
#define ET      (BE + BN_TOT)      // 278528 edges incl. self loops
#define NEG     0.2f
#define CAP     96                 // per-dst bucket capacity (Poisson(17) tail ~1e-50)

// ---------------- scratch (static device globals; no allocation) ----------------
__device__ __half g_xt[(size_t)BN_TOT * F];    // projected features, fp16, 16 MB
__device__ float  g_asrc[BN_TOT * Hh];         // per-node src attention dot (fp32)
__device__ float  g_adst[BN_TOT * Hh];         // per-node dst attention dot (fp32)
__device__ int    g_cnt[BN_TOT];               // in-degree / bucket fill
__device__ int    g_bucket[(size_t)BN_TOT * CAP];  // per-dst src lists, 6.3 MB

// ---------------- decode edges (+ self loops) straight into dst buckets ---------
// One pass replaces count+scan+place. 4 edges per thread, vectorized loads.
// Edge dtype (int64 vs silently-int32) detected per-warp ballot (converged).
__global__ void decode_place_kernel(const void* __restrict__ eiv) {
    const unsigned* w = (const unsigned*)eiv;
    unsigned hv = w[2 * (threadIdx.x & 31) + 1];
    int is64 = __all_sync(0xffffffffu, hv == 0u);

    int e0 = (blockIdx.x * blockDim.x + threadIdx.x) * 4;
    if (e0 >= ET) return;

    int s[4], d[4];
    if (e0 < BE) {                       // BE % 4 == 0: quad never straddles BE
        int k = e0 & (Ee - 1);           // Ee % 4 == 0: quad stays in one block b
        int off = (e0 >> 15) * Nn;
        if (is64) {
            const long long* p = (const long long*)eiv;
            longlong2 s01 = *(const longlong2*)(p + k);
            longlong2 s23 = *(const longlong2*)(p + k + 2);
            longlong2 d01 = *(const longlong2*)(p + Ee + k);
            longlong2 d23 = *(const longlong2*)(p + Ee + k + 2);
            s[0] = (int)s01.x; s[1] = (int)s01.y; s[2] = (int)s23.x; s[3] = (int)s23.y;
            d[0] = (int)d01.x; d[1] = (int)d01.y; d[2] = (int)d23.x; d[3] = (int)d23.y;
        } else {
            const int* p = (const int*)eiv;
            int4 sv = *(const int4*)(p + k);
            int4 dv = *(const int4*)(p + Ee + k);
            s[0] = sv.x; s[1] = sv.y; s[2] = sv.z; s[3] = sv.w;
            d[0] = dv.x; d[1] = dv.y; d[2] = dv.z; d[3] = dv.w;
        }
#pragma unroll
        for (int i = 0; i < 4; i++) { s[i] += off; d[i] += off; }
    } else {                             // self loops (ET-BE) % 4 == 0
#pragma unroll
        for (int i = 0; i < 4; i++) { s[i] = d[i] = e0 - BE + i; }
    }

#pragma unroll
    for (int i = 0; i < 4; i++) {
        int slot = atomicAdd(&g_cnt[d[i]], 1);
        if (slot < CAP) g_bucket[(size_t)d[i] * CAP + slot] = s[i];
    }
}

// ---------------- fp16 tensor-core GEMM (mma.sync m16n8k16, fp32 acc) -----------
// xt[16384,512] = x[16384,256] @ W[256,512], column-chunked by bx0 (chunk = 4 heads).
// 128x128 block tile, BK=32 (fp16), 256 threads = 8 warps in 4x2; warp tile 32x64.
#define BKH 32

#define MMA_F16(d, a, b)                                                          \
    asm volatile("mma.sync.aligned.m16n8k16.row.col.f32.f16.f16.f32 "             \
                 "{%0,%1,%2,%3}, {%4,%5,%6,%7}, {%8,%9}, {%0,%1,%2,%3};"          \
                 : "+f"(d[0]), "+f"(d[1]), "+f"(d[2]), "+f"(d[3])                  \
                 : "r"(a[0]), "r"(a[1]), "r"(a[2]), "r"(a[3]), "r"(b[0]), "r"(b[1]))

__global__ void __launch_bounds__(256, 2)
gemm_kernel(const float* __restrict__ A, const float* __restrict__ Bw,
            const float* __restrict__ att_src,
            const float* __restrict__ att_dst, int bx0) {
    __shared__ __half   As[128][40];     // [m][k] fp16, conflict-free (banks 20*qr+qc)
    __shared__ unsigned Bp[16][136];     // [k2][n] half2{k even, k odd}, conflict-free

    const int tid  = threadIdx.x;
    const int lane = tid & 31;
    const int wid  = tid >> 5;
    const int wr   = wid >> 1;           // 0..3
    const int wc   = wid & 1;            // 0..1
    const int bx   = bx0 + blockIdx.x;   // 0..3
    const int by   = blockIdx.y;         // 0..127
    const int qr   = lane >> 2;          // 0..7
    const int qc   = lane & 3;           // 0..3

    float acc[2][8][4];
#pragma unroll
    for (int i = 0; i < 2; i++)
#pragma unroll
        for (int j = 0; j < 8; j++)
#pragma unroll
            for (int k = 0; k < 4; k++) acc[i][j][k] = 0.0f;

    for (int k0 = 0; k0 < Cc; k0 += BKH) {
#pragma unroll
        for (int i = 0; i < 4; i++) {
            int idx = tid + i * 256;
            int r  = idx >> 3;
            int c4 = (idx & 7) << 2;
            float4 v = *(const float4*)(A + (size_t)(by * 128 + r) * Cc + k0 + c4);
            *(__half2*)&As[r][c4]     = __floats2half2_rn(v.x, v.y);
            *(__half2*)&As[r][c4 + 2] = __floats2half2_rn(v.z, v.w);
        }
#pragma unroll
        for (int i = 0; i < 2; i++) {
            int idx = tid + i * 256;
            int k2 = idx >> 5;
            int n4 = (idx & 31) << 2;
            const float* bp = Bw + (size_t)(k0 + 2 * k2) * F + bx * 128 + n4;
            float4 ev = *(const float4*)(bp);
            float4 ov = *(const float4*)(bp + F);
            __half2* dst = (__half2*)&Bp[k2][n4];
            dst[0] = __floats2half2_rn(ev.x, ov.x);
            dst[1] = __floats2half2_rn(ev.y, ov.y);
            dst[2] = __floats2half2_rn(ev.z, ov.z);
            dst[3] = __floats2half2_rn(ev.w, ov.w);
        }
        __syncthreads();

#pragma unroll
        for (int ks = 0; ks < 2; ks++) {
            unsigned a[2][4];
            const int kk = ks * 16 + 2 * qc;
#pragma unroll
            for (int mt = 0; mt < 2; mt++) {
                int rm = wr * 32 + mt * 16 + qr;
                a[mt][0] = *(const unsigned*)&As[rm][kk];
                a[mt][1] = *(const unsigned*)&As[rm + 8][kk];
                a[mt][2] = *(const unsigned*)&As[rm][kk + 8];
                a[mt][3] = *(const unsigned*)&As[rm + 8][kk + 8];
            }
            unsigned b[8][2];
            const int kb = ks * 8 + qc;
#pragma unroll
            for (int nt = 0; nt < 8; nt++) {
                int col = wc * 64 + nt * 8 + qr;
                b[nt][0] = Bp[kb][col];
                b[nt][1] = Bp[kb + 4][col];
            }
#pragma unroll
            for (int mt = 0; mt < 2; mt++)
#pragma unroll
                for (int nt = 0; nt < 8; nt++)
                    MMA_F16(acc[mt][nt], a[mt], b[nt]);
        }
        __syncthreads();
    }

    // epilogue: fp16 xt store
#pragma unroll
    for (int mt = 0; mt < 2; mt++) {
        int r = by * 128 + wr * 32 + mt * 16 + qr;
#pragma unroll
        for (int nt = 0; nt < 8; nt++) {
            int c = bx * 128 + wc * 64 + nt * 8 + 2 * qc;
            *(__half2*)(g_xt + (size_t)r * F + c) =
                __floats2half2_rn(acc[mt][nt][0], acc[mt][nt][1]);
            *(__half2*)(g_xt + (size_t)(r + 8) * F + c) =
                __floats2half2_rn(acc[mt][nt][2], acc[mt][nt][3]);
        }
    }

    // fused attdot (fp32 accumulators): head h = bx*2 + wc
    {
        const int h = bx * 2 + wc;
        const float* asv = att_src + h * CO;
        const float* adv = att_dst + h * CO;
        float s_att[16], d_att[16];
#pragma unroll
        for (int nt = 0; nt < 8; nt++) {
            int c = nt * 8 + 2 * qc;
            s_att[2 * nt]     = asv[c];
            s_att[2 * nt + 1] = asv[c + 1];
            d_att[2 * nt]     = adv[c];
            d_att[2 * nt + 1] = adv[c + 1];
        }
#pragma unroll
        for (int mt = 0; mt < 2; mt++) {
            float s0 = 0.f, d0 = 0.f, s1 = 0.f, d1 = 0.f;
#pragma unroll
            for (int nt = 0; nt < 8; nt++) {
                s0 += acc[mt][nt][0] * s_att[2 * nt] + acc[mt][nt][1] * s_att[2 * nt + 1];
                d0 += acc[mt][nt][0] * d_att[2 * nt] + acc[mt][nt][1] * d_att[2 * nt + 1];
                s1 += acc[mt][nt][2] * s_att[2 * nt] + acc[mt][nt][3] * s_att[2 * nt + 1];
                d1 += acc[mt][nt][2] * d_att[2 * nt] + acc[mt][nt][3] * d_att[2 * nt + 1];
            }
#pragma unroll
            for (int o = 1; o <= 2; o <<= 1) {
                s0 += __shfl_xor_sync(0xffffffffu, s0, o);
                d0 += __shfl_xor_sync(0xffffffffu, d0, o);
                s1 += __shfl_xor_sync(0xffffffffu, s1, o);
                d1 += __shfl_xor_sync(0xffffffffu, d1, o);
            }
            if (qc == 0) {
                int n0 = by * 128 + wr * 32 + mt * 16 + qr;
                g_asrc[n0 * Hh + h] = s0;
                g_adst[n0 * Hh + h] = d0;
                g_asrc[(n0 + 8) * Hh + h] = s1;
                g_adst[(n0 + 8) * Hh + h] = d1;
            }
        }
    }
}

// ---------------- fused softmax + weighted gather for a 4-head group ------------
// One block per dst node; one warp per head. Bucketed edge lists (no rowptr).
__global__ void gather_kernel(float* __restrict__ out, const float* __restrict__ bias,
                              int hbase) {
    int n = blockIdx.x;
    int h = hbase + (threadIdx.x >> 5);
    int lane = threadIdx.x & 31;
    int deg = g_cnt[n];
    if (deg > CAP) deg = CAP;
    const int* bucket = g_bucket + (size_t)n * CAP;

    float adstv = g_adst[n * Hh + h];
    const __half* xb = g_xt + h * CO + lane * 2;

    float2 acc = make_float2(0.0f, 0.0f);

    if (deg <= 32) {
        int s = 0;
        float l = -1e30f;
        if (lane < deg) {
            s = bucket[lane];
            float t = g_asrc[s * Hh + h] + adstv;
            l = (t > 0.0f) ? t : NEG * t;
        }
        float m = l;
#pragma unroll
        for (int o = 16; o; o >>= 1) m = fmaxf(m, __shfl_xor_sync(0xffffffffu, m, o));
        float wgt = (lane < deg) ? expf(l - m) : 0.0f;
        float sum = wgt;
#pragma unroll
        for (int o = 16; o; o >>= 1) sum += __shfl_xor_sync(0xffffffffu, sum, o);
        float a = wgt / (sum + 1e-16f);

        for (int j = 0; j < deg; j++) {
            float aj = __shfl_sync(0xffffffffu, a, j);
            int   sj = __shfl_sync(0xffffffffu, s, j);
            float2 v = __half22float2(*(const __half2*)(xb + (size_t)sj * F));
            acc.x += aj * v.x;
            acc.y += aj * v.y;
        }
    } else {
        float m = -1e30f;
        for (int i = lane; i < deg; i += 32) {
            int s = bucket[i];
            float t = g_asrc[s * Hh + h] + adstv;
            t = (t > 0.0f) ? t : NEG * t;
            m = fmaxf(m, t);
        }
#pragma unroll
        for (int o = 16; o; o >>= 1) m = fmaxf(m, __shfl_xor_sync(0xffffffffu, m, o));

        float sum = 0.0f;
        for (int i = lane; i < deg; i += 32) {
            int s = bucket[i];
            float t = g_asrc[s * Hh + h] + adstv;
            t = (t > 0.0f) ? t : NEG * t;
            sum += expf(t - m);
        }
#pragma unroll
        for (int o = 16; o; o >>= 1) sum += __shfl_xor_sync(0xffffffffu, sum, o);
        float inv = 1.0f / (sum + 1e-16f);

        for (int base = 0; base < deg; base += 32) {
            int i = base + lane;
            int sreg = 0;
            float areg = 0.0f;
            if (i < deg) {
                sreg = bucket[i];
                float t = g_asrc[sreg * Hh + h] + adstv;
                t = (t > 0.0f) ? t : NEG * t;
                areg = expf(t - m) * inv;
            }
            int cnt = deg - base;
            if (cnt > 32) cnt = 32;
            for (int j = 0; j < cnt; j++) {
                float aj = __shfl_sync(0xffffffffu, areg, j);
                int   sj = __shfl_sync(0xffffffffu, sreg, j);
                float2 v = __half22float2(*(const __half2*)(xb + (size_t)sj * F));
                acc.x += aj * v.x;
                acc.y += aj * v.y;
            }
        }
    }

    int c = h * CO + lane * 2;
    float2 bv = *(const float2*)(bias + c);
    *(float2*)(out + (size_t)n * F + c) = make_float2(acc.x + bv.x, acc.y + bv.y);
}

// ---------------- launch: bucket build || 2-chunk GEMM, concurrent gathers ------
extern "C" void kernel_launch(void* const* d_in, const int* in_sizes, int n_in,
                              void* d_out, int out_size) {
    const float* x    = (const float*)d_in[0];
    const void*  ei   = d_in[1];
    const float* W    = (const float*)d_in[2];
    const float* asrc = (const float*)d_in[3];
    const float* adst = (const float*)d_in[4];
    const float* bias = (const float*)d_in[5];
    float* out = (float*)d_out;

    static cudaStream_t s2 = nullptr;
    static cudaEvent_t ev_fork = nullptr, ev_g0 = nullptr, ev_csr = nullptr, ev_done = nullptr;
    static void* cnt_ptr = nullptr;
    if (s2 == nullptr) {
        cudaStreamCreateWithFlags(&s2, cudaStreamNonBlocking);
        cudaEventCreateWithFlags(&ev_fork, cudaEventDisableTiming);
        cudaEventCreateWithFlags(&ev_g0, cudaEventDisableTiming);
        cudaEventCreateWithFlags(&ev_csr, cudaEventDisableTiming);
        cudaEventCreateWithFlags(&ev_done, cudaEventDisableTiming);
        cudaGetSymbolAddress(&cnt_ptr, g_cnt);
    }

    cudaEventRecord(ev_fork, 0);
    cudaStreamWaitEvent(s2, ev_fork, 0);

    // s2: GEMM chunk 0 (heads 0..3), then chunk 1 (heads 4..7)
    gemm_kernel<<<dim3(2, BN_TOT / 128), 256, 0, s2>>>(x, W, asrc, adst, 0);
    cudaEventRecord(ev_g0, s2);
    gemm_kernel<<<dim3(2, BN_TOT / 128), 256, 0, s2>>>(x, W, asrc, adst, 2);

    // main: bucket build (one pass, no scan/place)
    cudaMemsetAsync(cnt_ptr, 0, BN_TOT * sizeof(int), 0);
    decode_place_kernel<<<(ET / 4 + 255) / 256, 256>>>(ei);
    cudaEventRecord(ev_csr, 0);

    // s2: gather heads 4..7 (after GEMM1 by stream order, buckets via ev_csr)
    cudaStreamWaitEvent(s2, ev_csr, 0);
    gather_kernel<<<BN_TOT, 128, 0, s2>>>(out, bias, 4);
    cudaEventRecord(ev_done, s2);

    // main: gather heads 0..3 (needs GEMM chunk 0 + buckets), runs concurrently
    cudaStreamWaitEvent(0, ev_g0, 0);
    gather_kernel<<<BN_TOT, 128>>>(out, bias, 0);

    // join
    cudaStreamWaitEvent(0, ev_done, 0);
}

// round 12
// speedup vs baseline: 2.1275x; 1.0137x over previous
#include <cuda_runtime.h>
#include <cuda_fp16.h>
#include <math.h>

// Problem constants
#define Bb      8
#define Nn      2048
#define Cc      256
#define Ee      32768
#define Hh      8
#define CO      64
#define BN_TOT  (Bb * Nn)          // 16384 nodes
#define F       (Hh * CO)          // 512 features
#define BE      (Bb * Ee)          // 262144 real edges
#define ET      (BE + BN_TOT)      // 278528 edges incl. self loops
#define NEG     0.2f
#define CAP     96                 // per-dst bucket capacity (Poisson(17) tail ~1e-50)

// ---------------- scratch (static device globals; no allocation) ----------------
__device__ __half g_xt[(size_t)BN_TOT * F];    // projected features, fp16, 16 MB
__device__ float  g_asrc[BN_TOT * Hh];         // per-node src attention dot (fp32)
__device__ float  g_adst[BN_TOT * Hh];         // per-node dst attention dot (fp32)
__device__ int    g_cnt[BN_TOT];               // in-degree / bucket fill
__device__ int    g_bucket[(size_t)BN_TOT * CAP];  // per-dst src lists, 6.3 MB

// ---------------- decode edges (+ self loops) straight into dst buckets ---------
__global__ void decode_place_kernel(const void* __restrict__ eiv) {
    const unsigned* w = (const unsigned*)eiv;
    unsigned hv = w[2 * (threadIdx.x & 31) + 1];
    int is64 = __all_sync(0xffffffffu, hv == 0u);

    int e0 = (blockIdx.x * blockDim.x + threadIdx.x) * 4;
    if (e0 >= ET) return;

    int s[4], d[4];
    if (e0 < BE) {                       // BE % 4 == 0: quad never straddles BE
        int k = e0 & (Ee - 1);
        int off = (e0 >> 15) * Nn;
        if (is64) {
            const long long* p = (const long long*)eiv;
            longlong2 s01 = *(const longlong2*)(p + k);
            longlong2 s23 = *(const longlong2*)(p + k + 2);
            longlong2 d01 = *(const longlong2*)(p + Ee + k);
            longlong2 d23 = *(const longlong2*)(p + Ee + k + 2);
            s[0] = (int)s01.x; s[1] = (int)s01.y; s[2] = (int)s23.x; s[3] = (int)s23.y;
            d[0] = (int)d01.x; d[1] = (int)d01.y; d[2] = (int)d23.x; d[3] = (int)d23.y;
        } else {
            const int* p = (const int*)eiv;
            int4 sv = *(const int4*)(p + k);
            int4 dv = *(const int4*)(p + Ee + k);
            s[0] = sv.x; s[1] = sv.y; s[2] = sv.z; s[3] = sv.w;
            d[0] = dv.x; d[1] = dv.y; d[2] = dv.z; d[3] = dv.w;
        }
#pragma unroll
        for (int i = 0; i < 4; i++) { s[i] += off; d[i] += off; }
    } else {
#pragma unroll
        for (int i = 0; i < 4; i++) { s[i] = d[i] = e0 - BE + i; }
    }

#pragma unroll
    for (int i = 0; i < 4; i++) {
        int slot = atomicAdd(&g_cnt[d[i]], 1);
        if (slot < CAP) g_bucket[(size_t)d[i] * CAP + slot] = s[i];
    }
}

// ---------------- fp16 tensor-core GEMM (mma.sync m16n8k16, fp32 acc) -----------
#define BKH 32

#define MMA_F16(d, a, b)                                                          \
    asm volatile("mma.sync.aligned.m16n8k16.row.col.f32.f16.f16.f32 "             \
                 "{%0,%1,%2,%3}, {%4,%5,%6,%7}, {%8,%9}, {%0,%1,%2,%3};"          \
                 : "+f"(d[0]), "+f"(d[1]), "+f"(d[2]), "+f"(d[3])                  \
                 : "r"(a[0]), "r"(a[1]), "r"(a[2]), "r"(a[3]), "r"(b[0]), "r"(b[1]))

__global__ void __launch_bounds__(256, 2)
gemm_kernel(const float* __restrict__ A, const float* __restrict__ Bw,
            const float* __restrict__ att_src,
            const float* __restrict__ att_dst, int bx0) {
    __shared__ __half   As[128][40];
    __shared__ unsigned Bp[16][136];

    const int tid  = threadIdx.x;
    const int lane = tid & 31;
    const int wid  = tid >> 5;
    const int wr   = wid >> 1;
    const int wc   = wid & 1;
    const int bx   = bx0 + blockIdx.x;
    const int by   = blockIdx.y;
    const int qr   = lane >> 2;
    const int qc   = lane & 3;

    float acc[2][8][4];
#pragma unroll
    for (int i = 0; i < 2; i++)
#pragma unroll
        for (int j = 0; j < 8; j++)
#pragma unroll
            for (int k = 0; k < 4; k++) acc[i][j][k] = 0.0f;

    for (int k0 = 0; k0 < Cc; k0 += BKH) {
#pragma unroll
        for (int i = 0; i < 4; i++) {
            int idx = tid + i * 256;
            int r  = idx >> 3;
            int c4 = (idx & 7) << 2;
            float4 v = *(const float4*)(A + (size_t)(by * 128 + r) * Cc + k0 + c4);
            *(__half2*)&As[r][c4]     = __floats2half2_rn(v.x, v.y);
            *(__half2*)&As[r][c4 + 2] = __floats2half2_rn(v.z, v.w);
        }
#pragma unroll
        for (int i = 0; i < 2; i++) {
            int idx = tid + i * 256;
            int k2 = idx >> 5;
            int n4 = (idx & 31) << 2;
            const float* bp = Bw + (size_t)(k0 + 2 * k2) * F + bx * 128 + n4;
            float4 ev = *(const float4*)(bp);
            float4 ov = *(const float4*)(bp + F);
            __half2* dst = (__half2*)&Bp[k2][n4];
            dst[0] = __floats2half2_rn(ev.x, ov.x);
            dst[1] = __floats2half2_rn(ev.y, ov.y);
            dst[2] = __floats2half2_rn(ev.z, ov.z);
            dst[3] = __floats2half2_rn(ev.w, ov.w);
        }
        __syncthreads();

#pragma unroll
        for (int ks = 0; ks < 2; ks++) {
            unsigned a[2][4];
            const int kk = ks * 16 + 2 * qc;
#pragma unroll
            for (int mt = 0; mt < 2; mt++) {
                int rm = wr * 32 + mt * 16 + qr;
                a[mt][0] = *(const unsigned*)&As[rm][kk];
                a[mt][1] = *(const unsigned*)&As[rm + 8][kk];
                a[mt][2] = *(const unsigned*)&As[rm][kk + 8];
                a[mt][3] = *(const unsigned*)&As[rm + 8][kk + 8];
            }
            unsigned b[8][2];
            const int kb = ks * 8 + qc;
#pragma unroll
            for (int nt = 0; nt < 8; nt++) {
                int col = wc * 64 + nt * 8 + qr;
                b[nt][0] = Bp[kb][col];
                b[nt][1] = Bp[kb + 4][col];
            }
#pragma unroll
            for (int mt = 0; mt < 2; mt++)
#pragma unroll
                for (int nt = 0; nt < 8; nt++)
                    MMA_F16(acc[mt][nt], a[mt], b[nt]);
        }
        __syncthreads();
    }

#pragma unroll
    for (int mt = 0; mt < 2; mt++) {
        int r = by * 128 + wr * 32 + mt * 16 + qr;
#pragma unroll
        for (int nt = 0; nt < 8; nt++) {
            int c = bx * 128 + wc * 64 + nt * 8 + 2 * qc;
            *(__half2*)(g_xt + (size_t)r * F + c) =
                __floats2half2_rn(acc[mt][nt][0], acc[mt][nt][1]);
            *(__half2*)(g_xt + (size_t)(r + 8) * F + c) =
                __floats2half2_rn(acc[mt][nt][2], acc[mt][nt][3]);
        }
    }

    {
        const int h = bx * 2 + wc;
        const float* asv = att_src + h * CO;
        const float* adv = att_dst + h * CO;
        float s_att[16], d_att[16];
#pragma unroll
        for (int nt = 0; nt < 8; nt++) {
            int c = nt * 8 + 2 * qc;
            s_att[2 * nt]     = asv[c];
            s_att[2 * nt + 1] = asv[c + 1];
            d_att[2 * nt]     = adv[c];
            d_att[2 * nt + 1] = adv[c + 1];
        }
#pragma unroll
        for (int mt = 0; mt < 2; mt++) {
            float s0 = 0.f, d0 = 0.f, s1 = 0.f, d1 = 0.f;
#pragma unroll
            for (int nt = 0; nt < 8; nt++) {
                s0 += acc[mt][nt][0] * s_att[2 * nt] + acc[mt][nt][1] * s_att[2 * nt + 1];
                d0 += acc[mt][nt][0] * d_att[2 * nt] + acc[mt][nt][1] * d_att[2 * nt + 1];
                s1 += acc[mt][nt][2] * s_att[2 * nt] + acc[mt][nt][3] * s_att[2 * nt + 1];
                d1 += acc[mt][nt][2] * d_att[2 * nt] + acc[mt][nt][3] * d_att[2 * nt + 1];
            }
#pragma unroll
            for (int o = 1; o <= 2; o <<= 1) {
                s0 += __shfl_xor_sync(0xffffffffu, s0, o);
                d0 += __shfl_xor_sync(0xffffffffu, d0, o);
                s1 += __shfl_xor_sync(0xffffffffu, s1, o);
                d1 += __shfl_xor_sync(0xffffffffu, d1, o);
            }
            if (qc == 0) {
                int n0 = by * 128 + wr * 32 + mt * 16 + qr;
                g_asrc[n0 * Hh + h] = s0;
                g_adst[n0 * Hh + h] = d0;
                g_asrc[(n0 + 8) * Hh + h] = s1;
                g_adst[(n0 + 8) * Hh + h] = d1;
            }
        }
    }
}

// ---------------- fused softmax + weighted gather for a 4-head group ------------
// One block per dst node; one warp per head. 4 edges per iteration:
// lane group q=lane>>3 handles edge j+q; each lane loads 8 channels (LDG.128).
// Broadcast via 2 dynamic-index shuffles per iteration (converged).
__global__ void gather_kernel(float* __restrict__ out, const float* __restrict__ bias,
                              int hbase) {
    int n = blockIdx.x;
    int h = hbase + (threadIdx.x >> 5);
    int lane = threadIdx.x & 31;
    int q = lane >> 3;                    // edge-subgroup 0..3
    int cl = lane & 7;                    // channel-lane: 8 halves each
    int deg = g_cnt[n];
    if (deg > CAP) deg = CAP;
    const int* bucket = g_bucket + (size_t)n * CAP;

    float adstv = g_adst[n * Hh + h];
    const __half* xb = g_xt + h * CO + cl * 8;

    float acc[8] = {0.f, 0.f, 0.f, 0.f, 0.f, 0.f, 0.f, 0.f};

    if (deg <= 32) {
        // softmax fully in registers: one logit + one expf per edge-head
        int s = 0;
        float l = -1e30f;
        if (lane < deg) {
            s = bucket[lane];
            float t = g_asrc[s * Hh + h] + adstv;
            l = (t > 0.0f) ? t : NEG * t;
        }
        float m = l;
#pragma unroll
        for (int o = 16; o; o >>= 1) m = fmaxf(m, __shfl_xor_sync(0xffffffffu, m, o));
        float wgt = (lane < deg) ? expf(l - m) : 0.0f;
        float sum = wgt;
#pragma unroll
        for (int o = 16; o; o >>= 1) sum += __shfl_xor_sync(0xffffffffu, sum, o);
        float a = wgt / (sum + 1e-16f);   // 0 for padding lanes (s=0 loads node 0, a=0)

        int dr = (deg + 3) & ~3;          // <= 32
        for (int j = 0; j < dr; j += 4) {
            float aj = __shfl_sync(0xffffffffu, a, j + q);
            int   sj = __shfl_sync(0xffffffffu, s, j + q);
            uint4 u = *(const uint4*)(xb + (size_t)sj * F);
            float2 f0 = __half22float2(*(__half2*)&u.x);
            float2 f1 = __half22float2(*(__half2*)&u.y);
            float2 f2 = __half22float2(*(__half2*)&u.z);
            float2 f3 = __half22float2(*(__half2*)&u.w);
            acc[0] += aj * f0.x; acc[1] += aj * f0.y;
            acc[2] += aj * f1.x; acc[3] += aj * f1.y;
            acc[4] += aj * f2.x; acc[5] += aj * f2.y;
            acc[6] += aj * f3.x; acc[7] += aj * f3.y;
        }
    } else {
        // general path (rare): two reduction passes + chunked 4-edge accumulation
        float m = -1e30f;
        for (int i = lane; i < deg; i += 32) {
            int s = bucket[i];
            float t = g_asrc[s * Hh + h] + adstv;
            t = (t > 0.0f) ? t : NEG * t;
            m = fmaxf(m, t);
        }
#pragma unroll
        for (int o = 16; o; o >>= 1) m = fmaxf(m, __shfl_xor_sync(0xffffffffu, m, o));

        float sum = 0.0f;
        for (int i = lane; i < deg; i += 32) {
            int s = bucket[i];
            float t = g_asrc[s * Hh + h] + adstv;
            t = (t > 0.0f) ? t : NEG * t;
            sum += expf(t - m);
        }
#pragma unroll
        for (int o = 16; o; o >>= 1) sum += __shfl_xor_sync(0xffffffffu, sum, o);
        float inv = 1.0f / (sum + 1e-16f);

        for (int base = 0; base < deg; base += 32) {
            int i = base + lane;
            int sreg = 0;
            float areg = 0.0f;
            if (i < deg) {
                sreg = bucket[i];
                float t = g_asrc[sreg * Hh + h] + adstv;
                t = (t > 0.0f) ? t : NEG * t;
                areg = expf(t - m) * inv;
            }
            int cnt = deg - base;
            if (cnt > 32) cnt = 32;
            int cr = (cnt + 3) & ~3;
            for (int j = 0; j < cr; j += 4) {
                float aj = __shfl_sync(0xffffffffu, areg, j + q);
                int   sj = __shfl_sync(0xffffffffu, sreg, j + q);
                uint4 u = *(const uint4*)(xb + (size_t)sj * F);
                float2 f0 = __half22float2(*(__half2*)&u.x);
                float2 f1 = __half22float2(*(__half2*)&u.y);
                float2 f2 = __half22float2(*(__half2*)&u.z);
                float2 f3 = __half22float2(*(__half2*)&u.w);
                acc[0] += aj * f0.x; acc[1] += aj * f0.y;
                acc[2] += aj * f1.x; acc[3] += aj * f1.y;
                acc[4] += aj * f2.x; acc[5] += aj * f2.y;
                acc[6] += aj * f3.x; acc[7] += aj * f3.y;
            }
        }
    }

    // fold the 4 edge-subgroups (lanes 8,16 apart hold same channels)
#pragma unroll
    for (int i = 0; i < 8; i++) {
        acc[i] += __shfl_xor_sync(0xffffffffu, acc[i], 8);
        acc[i] += __shfl_xor_sync(0xffffffffu, acc[i], 16);
    }

    if (q == 0) {                          // lanes 0..7 write 8 channels each
        int c = h * CO + cl * 8;
        float4 b0 = *(const float4*)(bias + c);
        float4 b1 = *(const float4*)(bias + c + 4);
        float* o = out + (size_t)n * F + c;
        *(float4*)(o)     = make_float4(acc[0] + b0.x, acc[1] + b0.y,
                                        acc[2] + b0.z, acc[3] + b0.w);
        *(float4*)(o + 4) = make_float4(acc[4] + b1.x, acc[5] + b1.y,
                                        acc[6] + b1.z, acc[7] + b1.w);
    }
}

// ---------------- launch: bucket build || 2-chunk GEMM, pipelined gathers -------
extern "C" void kernel_launch(void* const* d_in, const int* in_sizes, int n_in,
                              void* d_out, int out_size) {
    const float* x    = (const float*)d_in[0];
    const void*  ei   = d_in[1];
    const float* W    = (const float*)d_in[2];
    const float* asrc = (const float*)d_in[3];
    const float* adst = (const float*)d_in[4];
    const float* bias = (const float*)d_in[5];
    float* out = (float*)d_out;

    static cudaStream_t s2 = nullptr;
    static cudaEvent_t ev_fork = nullptr, ev_g0 = nullptr, ev_csr = nullptr, ev_done = nullptr;
    static void* cnt_ptr = nullptr;
    if (s2 == nullptr) {
        cudaStreamCreateWithFlags(&s2, cudaStreamNonBlocking);
        cudaEventCreateWithFlags(&ev_fork, cudaEventDisableTiming);
        cudaEventCreateWithFlags(&ev_g0, cudaEventDisableTiming);
        cudaEventCreateWithFlags(&ev_csr, cudaEventDisableTiming);
        cudaEventCreateWithFlags(&ev_done, cudaEventDisableTiming);
        cudaGetSymbolAddress(&cnt_ptr, g_cnt);
    }

    cudaEventRecord(ev_fork, 0);
    cudaStreamWaitEvent(s2, ev_fork, 0);

    // s2: GEMM chunk 0 (heads 0..3), then chunk 1 (heads 4..7)
    gemm_kernel<<<dim3(2, BN_TOT / 128), 256, 0, s2>>>(x, W, asrc, adst, 0);
    cudaEventRecord(ev_g0, s2);
    gemm_kernel<<<dim3(2, BN_TOT / 128), 256, 0, s2>>>(x, W, asrc, adst, 2);

    // main: bucket build (one pass, no scan/place)
    cudaMemsetAsync(cnt_ptr, 0, BN_TOT * sizeof(int), 0);
    decode_place_kernel<<<(ET / 4 + 255) / 256, 256>>>(ei);
    cudaEventRecord(ev_csr, 0);

    // s2: gather heads 4..7 (after GEMM1 by stream order, buckets via ev_csr)
    cudaStreamWaitEvent(s2, ev_csr, 0);
    gather_kernel<<<BN_TOT, 128, 0, s2>>>(out, bias, 4);
    cudaEventRecord(ev_done, s2);

    // main: gather heads 0..3 (needs GEMM chunk 0 + buckets)
    cudaStreamWaitEvent(0, ev_g0, 0);
    gather_kernel<<<BN_TOT, 128>>>(out, bias, 0);

    // join
    cudaStreamWaitEvent(0, ev_done, 0);
}

// round 13
// speedup vs baseline: 2.1976x; 1.0329x over previous
#include <cuda_runtime.h>
#include <cuda_fp16.h>
#include <math.h>

// Problem constants
#define Bb      8
#define Nn      2048
#define Cc      256
#define Ee      32768
#define Hh      8
#define CO      64
#define BN_TOT  (Bb * Nn)          // 16384 nodes
#define F       (Hh * CO)          // 512 features
#define BE      (Bb * Ee)          // 262144 real edges
#define ET      (BE + BN_TOT)      // 278528 edges incl. self loops
#define NEG     0.2f
#define CAP     96                 // per-dst bucket capacity (Poisson(17) tail ~1e-50)

// ---------------- scratch (static device globals; no allocation) ----------------
__device__ __half g_xt[(size_t)BN_TOT * F];    // projected features, fp16, 16 MB
__device__ float  g_asrc[BN_TOT * Hh];         // per-node src attention dot (fp32)
__device__ float  g_adst[BN_TOT * Hh];         // per-node dst attention dot (fp32)
__device__ int    g_cnt[BN_TOT];               // in-degree / bucket fill
__device__ int    g_bucket[(size_t)BN_TOT * CAP];  // per-dst src lists, 6.3 MB

// ---------------- decode edges (+ self loops) straight into dst buckets ---------
__global__ void decode_place_kernel(const void* __restrict__ eiv) {
    const unsigned* w = (const unsigned*)eiv;
    unsigned hv = w[2 * (threadIdx.x & 31) + 1];
    int is64 = __all_sync(0xffffffffu, hv == 0u);

    int e0 = (blockIdx.x * blockDim.x + threadIdx.x) * 4;
    if (e0 >= ET) return;

    int s[4], d[4];
    if (e0 < BE) {                       // BE % 4 == 0: quad never straddles BE
        int k = e0 & (Ee - 1);
        int off = (e0 >> 15) * Nn;
        if (is64) {
            const long long* p = (const long long*)eiv;
            longlong2 s01 = *(const longlong2*)(p + k);
            longlong2 s23 = *(const longlong2*)(p + k + 2);
            longlong2 d01 = *(const longlong2*)(p + Ee + k);
            longlong2 d23 = *(const longlong2*)(p + Ee + k + 2);
            s[0] = (int)s01.x; s[1] = (int)s01.y; s[2] = (int)s23.x; s[3] = (int)s23.y;
            d[0] = (int)d01.x; d[1] = (int)d01.y; d[2] = (int)d23.x; d[3] = (int)d23.y;
        } else {
            const int* p = (const int*)eiv;
            int4 sv = *(const int4*)(p + k);
            int4 dv = *(const int4*)(p + Ee + k);
            s[0] = sv.x; s[1] = sv.y; s[2] = sv.z; s[3] = sv.w;
            d[0] = dv.x; d[1] = dv.y; d[2] = dv.z; d[3] = dv.w;
        }
#pragma unroll
        for (int i = 0; i < 4; i++) { s[i] += off; d[i] += off; }
    } else {
#pragma unroll
        for (int i = 0; i < 4; i++) { s[i] = d[i] = e0 - BE + i; }
    }

#pragma unroll
    for (int i = 0; i < 4; i++) {
        int slot = atomicAdd(&g_cnt[d[i]], 1);
        if (slot < CAP) g_bucket[(size_t)d[i] * CAP + slot] = s[i];
    }
}

// ---------------- fp16 tensor-core GEMM (mma.sync m16n8k16, fp32 acc) -----------
#define BKH 32

#define MMA_F16(d, a, b)                                                          \
    asm volatile("mma.sync.aligned.m16n8k16.row.col.f32.f16.f16.f32 "             \
                 "{%0,%1,%2,%3}, {%4,%5,%6,%7}, {%8,%9}, {%0,%1,%2,%3};"          \
                 : "+f"(d[0]), "+f"(d[1]), "+f"(d[2]), "+f"(d[3])                  \
                 : "r"(a[0]), "r"(a[1]), "r"(a[2]), "r"(a[3]), "r"(b[0]), "r"(b[1]))

__global__ void __launch_bounds__(256, 2)
gemm_kernel(const float* __restrict__ A, const float* __restrict__ Bw,
            const float* __restrict__ att_src,
            const float* __restrict__ att_dst) {
    __shared__ __half   As[128][40];
    __shared__ unsigned Bp[16][136];

    const int tid  = threadIdx.x;
    const int lane = tid & 31;
    const int wid  = tid >> 5;
    const int wr   = wid >> 1;
    const int wc   = wid & 1;
    const int bx   = blockIdx.x;         // 0..3
    const int by   = blockIdx.y;         // 0..127
    const int qr   = lane >> 2;
    const int qc   = lane & 3;

    float acc[2][8][4];
#pragma unroll
    for (int i = 0; i < 2; i++)
#pragma unroll
        for (int j = 0; j < 8; j++)
#pragma unroll
            for (int k = 0; k < 4; k++) acc[i][j][k] = 0.0f;

    for (int k0 = 0; k0 < Cc; k0 += BKH) {
#pragma unroll
        for (int i = 0; i < 4; i++) {
            int idx = tid + i * 256;
            int r  = idx >> 3;
            int c4 = (idx & 7) << 2;
            float4 v = *(const float4*)(A + (size_t)(by * 128 + r) * Cc + k0 + c4);
            *(__half2*)&As[r][c4]     = __floats2half2_rn(v.x, v.y);
            *(__half2*)&As[r][c4 + 2] = __floats2half2_rn(v.z, v.w);
        }
#pragma unroll
        for (int i = 0; i < 2; i++) {
            int idx = tid + i * 256;
            int k2 = idx >> 5;
            int n4 = (idx & 31) << 2;
            const float* bp = Bw + (size_t)(k0 + 2 * k2) * F + bx * 128 + n4;
            float4 ev = *(const float4*)(bp);
            float4 ov = *(const float4*)(bp + F);
            __half2* dst = (__half2*)&Bp[k2][n4];
            dst[0] = __floats2half2_rn(ev.x, ov.x);
            dst[1] = __floats2half2_rn(ev.y, ov.y);
            dst[2] = __floats2half2_rn(ev.z, ov.z);
            dst[3] = __floats2half2_rn(ev.w, ov.w);
        }
        __syncthreads();

#pragma unroll
        for (int ks = 0; ks < 2; ks++) {
            unsigned a[2][4];
            const int kk = ks * 16 + 2 * qc;
#pragma unroll
            for (int mt = 0; mt < 2; mt++) {
                int rm = wr * 32 + mt * 16 + qr;
                a[mt][0] = *(const unsigned*)&As[rm][kk];
                a[mt][1] = *(const unsigned*)&As[rm + 8][kk];
                a[mt][2] = *(const unsigned*)&As[rm][kk + 8];
                a[mt][3] = *(const unsigned*)&As[rm + 8][kk + 8];
            }
            unsigned b[8][2];
            const int kb = ks * 8 + qc;
#pragma unroll
            for (int nt = 0; nt < 8; nt++) {
                int col = wc * 64 + nt * 8 + qr;
                b[nt][0] = Bp[kb][col];
                b[nt][1] = Bp[kb + 4][col];
            }
#pragma unroll
            for (int mt = 0; mt < 2; mt++)
#pragma unroll
                for (int nt = 0; nt < 8; nt++)
                    MMA_F16(acc[mt][nt], a[mt], b[nt]);
        }
        __syncthreads();
    }

#pragma unroll
    for (int mt = 0; mt < 2; mt++) {
        int r = by * 128 + wr * 32 + mt * 16 + qr;
#pragma unroll
        for (int nt = 0; nt < 8; nt++) {
            int c = bx * 128 + wc * 64 + nt * 8 + 2 * qc;
            *(__half2*)(g_xt + (size_t)r * F + c) =
                __floats2half2_rn(acc[mt][nt][0], acc[mt][nt][1]);
            *(__half2*)(g_xt + (size_t)(r + 8) * F + c) =
                __floats2half2_rn(acc[mt][nt][2], acc[mt][nt][3]);
        }
    }

    {
        const int h = bx * 2 + wc;
        const float* asv = att_src + h * CO;
        const float* adv = att_dst + h * CO;
        float s_att[16], d_att[16];
#pragma unroll
        for (int nt = 0; nt < 8; nt++) {
            int c = nt * 8 + 2 * qc;
            s_att[2 * nt]     = asv[c];
            s_att[2 * nt + 1] = asv[c + 1];
            d_att[2 * nt]     = adv[c];
            d_att[2 * nt + 1] = adv[c + 1];
        }
#pragma unroll
        for (int mt = 0; mt < 2; mt++) {
            float s0 = 0.f, d0 = 0.f, s1 = 0.f, d1 = 0.f;
#pragma unroll
            for (int nt = 0; nt < 8; nt++) {
                s0 += acc[mt][nt][0] * s_att[2 * nt] + acc[mt][nt][1] * s_att[2 * nt + 1];
                d0 += acc[mt][nt][0] * d_att[2 * nt] + acc[mt][nt][1] * d_att[2 * nt + 1];
                s1 += acc[mt][nt][2] * s_att[2 * nt] + acc[mt][nt][3] * s_att[2 * nt + 1];
                d1 += acc[mt][nt][2] * d_att[2 * nt] + acc[mt][nt][3] * d_att[2 * nt + 1];
            }
#pragma unroll
            for (int o = 1; o <= 2; o <<= 1) {
                s0 += __shfl_xor_sync(0xffffffffu, s0, o);
                d0 += __shfl_xor_sync(0xffffffffu, d0, o);
                s1 += __shfl_xor_sync(0xffffffffu, s1, o);
                d1 += __shfl_xor_sync(0xffffffffu, d1, o);
            }
            if (qc == 0) {
                int n0 = by * 128 + wr * 32 + mt * 16 + qr;
                g_asrc[n0 * Hh + h] = s0;
                g_adst[n0 * Hh + h] = d0;
                g_asrc[(n0 + 8) * Hh + h] = s1;
                g_adst[(n0 + 8) * Hh + h] = d1;
            }
        }
    }
}

// ---------------- fused softmax + weighted gather, ALL 8 heads per block --------
// 256 threads; warp w = head w. 8 edges per iteration (two interleaved quads,
// both LDG.128s in flight -> MLP=2). q = lane>>3 picks the edge within a quad,
// cl = lane&7 picks 8 channels (one uint4). Guard-free via alpha=0 padding.
__global__ void gather_kernel(float* __restrict__ out, const float* __restrict__ bias) {
    int n = blockIdx.x;
    int h = threadIdx.x >> 5;
    int lane = threadIdx.x & 31;
    int q = lane >> 3;                    // edge-subgroup 0..3
    int cl = lane & 7;                    // channel-lane: 8 halves each
    int deg = g_cnt[n];
    if (deg > CAP) deg = CAP;
    const int* bucket = g_bucket + (size_t)n * CAP;

    float adstv = g_adst[n * Hh + h];
    const __half* xb = g_xt + h * CO + cl * 8;

    float acc[8] = {0.f, 0.f, 0.f, 0.f, 0.f, 0.f, 0.f, 0.f};

    if (deg <= 32) {
        int s = 0;
        float l = -1e30f;
        if (lane < deg) {
            s = bucket[lane];
            float t = g_asrc[s * Hh + h] + adstv;
            l = (t > 0.0f) ? t : NEG * t;
        }
        float m = l;
#pragma unroll
        for (int o = 16; o; o >>= 1) m = fmaxf(m, __shfl_xor_sync(0xffffffffu, m, o));
        float wgt = (lane < deg) ? __expf(l - m) : 0.0f;
        float sum = wgt;
#pragma unroll
        for (int o = 16; o; o >>= 1) sum += __shfl_xor_sync(0xffffffffu, sum, o);
        float a = wgt / (sum + 1e-16f);   // 0 for padding lanes

        int dr = (deg + 7) & ~7;          // <= 32; shuffle idx j+4+q <= 31
        for (int j = 0; j < dr; j += 8) {
            float a0 = __shfl_sync(0xffffffffu, a, j + q);
            int   s0 = __shfl_sync(0xffffffffu, s, j + q);
            float a1 = __shfl_sync(0xffffffffu, a, j + 4 + q);
            int   s1 = __shfl_sync(0xffffffffu, s, j + 4 + q);
            uint4 u0 = *(const uint4*)(xb + (size_t)s0 * F);
            uint4 u1 = *(const uint4*)(xb + (size_t)s1 * F);
            float2 f0 = __half22float2(*(__half2*)&u0.x);
            float2 f1 = __half22float2(*(__half2*)&u0.y);
            float2 f2 = __half22float2(*(__half2*)&u0.z);
            float2 f3 = __half22float2(*(__half2*)&u0.w);
            acc[0] += a0 * f0.x; acc[1] += a0 * f0.y;
            acc[2] += a0 * f1.x; acc[3] += a0 * f1.y;
            acc[4] += a0 * f2.x; acc[5] += a0 * f2.y;
            acc[6] += a0 * f3.x; acc[7] += a0 * f3.y;
            f0 = __half22float2(*(__half2*)&u1.x);
            f1 = __half22float2(*(__half2*)&u1.y);
            f2 = __half22float2(*(__half2*)&u1.z);
            f3 = __half22float2(*(__half2*)&u1.w);
            acc[0] += a1 * f0.x; acc[1] += a1 * f0.y;
            acc[2] += a1 * f1.x; acc[3] += a1 * f1.y;
            acc[4] += a1 * f2.x; acc[5] += a1 * f2.y;
            acc[6] += a1 * f3.x; acc[7] += a1 * f3.y;
        }
    } else {
        // general path (rare): two reduction passes + chunked 8-edge accumulation
        float m = -1e30f;
        for (int i = lane; i < deg; i += 32) {
            int s = bucket[i];
            float t = g_asrc[s * Hh + h] + adstv;
            t = (t > 0.0f) ? t : NEG * t;
            m = fmaxf(m, t);
        }
#pragma unroll
        for (int o = 16; o; o >>= 1) m = fmaxf(m, __shfl_xor_sync(0xffffffffu, m, o));

        float sum = 0.0f;
        for (int i = lane; i < deg; i += 32) {
            int s = bucket[i];
            float t = g_asrc[s * Hh + h] + adstv;
            t = (t > 0.0f) ? t : NEG * t;
            sum += __expf(t - m);
        }
#pragma unroll
        for (int o = 16; o; o >>= 1) sum += __shfl_xor_sync(0xffffffffu, sum, o);
        float inv = 1.0f / (sum + 1e-16f);

        for (int base = 0; base < deg; base += 32) {
            int i = base + lane;
            int sreg = 0;
            float areg = 0.0f;
            if (i < deg) {
                sreg = bucket[i];
                float t = g_asrc[sreg * Hh + h] + adstv;
                t = (t > 0.0f) ? t : NEG * t;
                areg = __expf(t - m) * inv;
            }
            int cnt = deg - base;
            if (cnt > 32) cnt = 32;
            int cr = (cnt + 7) & ~7;
            for (int j = 0; j < cr; j += 8) {
                float a0 = __shfl_sync(0xffffffffu, areg, j + q);
                int   s0 = __shfl_sync(0xffffffffu, sreg, j + q);
                float a1 = __shfl_sync(0xffffffffu, areg, j + 4 + q);
                int   s1 = __shfl_sync(0xffffffffu, sreg, j + 4 + q);
                uint4 u0 = *(const uint4*)(xb + (size_t)s0 * F);
                uint4 u1 = *(const uint4*)(xb + (size_t)s1 * F);
                float2 f0 = __half22float2(*(__half2*)&u0.x);
                float2 f1 = __half22float2(*(__half2*)&u0.y);
                float2 f2 = __half22float2(*(__half2*)&u0.z);
                float2 f3 = __half22float2(*(__half2*)&u0.w);
                acc[0] += a0 * f0.x; acc[1] += a0 * f0.y;
                acc[2] += a0 * f1.x; acc[3] += a0 * f1.y;
                acc[4] += a0 * f2.x; acc[5] += a0 * f2.y;
                acc[6] += a0 * f3.x; acc[7] += a0 * f3.y;
                f0 = __half22float2(*(__half2*)&u1.x);
                f1 = __half22float2(*(__half2*)&u1.y);
                f2 = __half22float2(*(__half2*)&u1.z);
                f3 = __half22float2(*(__half2*)&u1.w);
                acc[0] += a1 * f0.x; acc[1] += a1 * f0.y;
                acc[2] += a1 * f1.x; acc[3] += a1 * f1.y;
                acc[4] += a1 * f2.x; acc[5] += a1 * f2.y;
                acc[6] += a1 * f3.x; acc[7] += a1 * f3.y;
            }
        }
    }

    // fold the 4 edge-subgroups (lanes 8,16 apart hold same channels)
#pragma unroll
    for (int i = 0; i < 8; i++) {
        acc[i] += __shfl_xor_sync(0xffffffffu, acc[i], 8);
        acc[i] += __shfl_xor_sync(0xffffffffu, acc[i], 16);
    }

    if (q == 0) {                          // lanes 0..7 write 8 channels each
        int c = h * CO + cl * 8;
        float4 b0 = *(const float4*)(bias + c);
        float4 b1 = *(const float4*)(bias + c + 4);
        float* o = out + (size_t)n * F + c;
        *(float4*)(o)     = make_float4(acc[0] + b0.x, acc[1] + b0.y,
                                        acc[2] + b0.z, acc[3] + b0.w);
        *(float4*)(o + 4) = make_float4(acc[4] + b1.x, acc[5] + b1.y,
                                        acc[6] + b1.z, acc[7] + b1.w);
    }
}

// ---------------- launch: bucket build || GEMM, then one merged gather ----------
extern "C" void kernel_launch(void* const* d_in, const int* in_sizes, int n_in,
                              void* d_out, int out_size) {
    const float* x    = (const float*)d_in[0];
    const void*  ei   = d_in[1];
    const float* W    = (const float*)d_in[2];
    const float* asrc = (const float*)d_in[3];
    const float* adst = (const float*)d_in[4];
    const float* bias = (const float*)d_in[5];
    float* out = (float*)d_out;

    static cudaStream_t s2 = nullptr;
    static cudaEvent_t ev_fork = nullptr, ev_gemm = nullptr;
    static void* cnt_ptr = nullptr;
    if (s2 == nullptr) {
        cudaStreamCreateWithFlags(&s2, cudaStreamNonBlocking);
        cudaEventCreateWithFlags(&ev_fork, cudaEventDisableTiming);
        cudaEventCreateWithFlags(&ev_gemm, cudaEventDisableTiming);
        cudaGetSymbolAddress(&cnt_ptr, g_cnt);
    }

    cudaEventRecord(ev_fork, 0);
    cudaStreamWaitEvent(s2, ev_fork, 0);

    // s2: full GEMM + fused attdot (512 blocks, 2 CTA/SM)
    gemm_kernel<<<dim3(4, BN_TOT / 128), 256, 0, s2>>>(x, W, asrc, adst);
    cudaEventRecord(ev_gemm, s2);

    // main: bucket build (one pass)
    cudaMemsetAsync(cnt_ptr, 0, BN_TOT * sizeof(int), 0);
    decode_place_kernel<<<(ET / 4 + 255) / 256, 256>>>(ei);

    // join: merged gather over all 8 heads
    cudaStreamWaitEvent(0, ev_gemm, 0);
    gather_kernel<<<BN_TOT, 256>>>(out, bias);
}